// round 3
// baseline (speedup 1.0000x reference)
#include <cuda_runtime.h>

#define N_NODES 100000
#define N_EDGES 600000
#define D 128
#define DIN 16
#define ND (N_NODES * D)

// ---------------- scratch (static __device__ arrays; no allocs) ----------------
__device__ float g_hnet[ND], g_hcell[ND];                 // projected features
__device__ float g_hs0[ND], g_hs1[ND], g_hs2[ND];         // h_src per relation
__device__ float g_bnet[ND], g_bcell[ND];                 // feat @ Wl1.T
__device__ float g_agg0[ND], g_agg1[ND], g_agg2[ND];      // normalized GAT outputs
__device__ float g_tmpA[ND], g_tmpB[ND];                  // chain intermediates
__device__ float g_el[3][N_NODES], g_er[3][N_NODES];
__device__ float g_vr0[D], g_vr1[D], g_bvec[D];
__device__ int   g_cnt[3][N_NODES];
__device__ int   g_rowptr[3][N_NODES + 1];
__device__ int   g_cursor[3][N_NODES];
__device__ int   g_csrc[3][N_EDGES];
__device__ float g_cw[3][N_EDGES];

// ---------------- feature projection: h = x @ Wp.T  ([N,16] -> [N,128]) --------
__global__ __launch_bounds__(256) void proj_kernel(
    const float* __restrict__ x, const float* __restrict__ Wp,
    float* __restrict__ h) {
    __shared__ float Ws[D * DIN];
    int tid = threadIdx.x;
    for (int i = tid; i < D * DIN; i += 256) Ws[i] = Wp[i];
    __syncthreads();
    int warp = tid >> 5, lane = tid & 31;
    int i = blockIdx.x * 8 + warp;
    if (i >= N_NODES) return;
    float xv = x[i * DIN + (lane & 15)];
    int k0 = lane * 4;
    float acc0 = 0.f, acc1 = 0.f, acc2 = 0.f, acc3 = 0.f;
#pragma unroll
    for (int j = 0; j < 16; j++) {
        float xj = __shfl_sync(0xffffffffu, xv, j);
        acc0 += xj * Ws[(k0 + 0) * 16 + j];
        acc1 += xj * Ws[(k0 + 1) * 16 + j];
        acc2 += xj * Ws[(k0 + 2) * 16 + j];
        acc3 += xj * Ws[(k0 + 3) * 16 + j];
    }
    float4 o = make_float4(acc0, acc1, acc2, acc3);
    *(float4*)&h[i * D + k0] = o;
}

// ---------------- attention vectors: vr0=W0.T@ar0, vr1=W1.T@ar1, bvec=Wl2@bias -
__global__ __launch_bounds__(128) void attnvec_kernel(
    const float* __restrict__ Wg0, const float* __restrict__ ar0,
    const float* __restrict__ Wg1, const float* __restrict__ ar1,
    const float* __restrict__ Wl, const float* __restrict__ bias) {
    int k = threadIdx.x;
    float s0 = 0.f, s1 = 0.f, sb = 0.f;
    for (int j = 0; j < D; j++) {
        s0 += Wg0[j * D + k] * ar0[j];
        s1 += Wg1[j * D + k] * ar1[j];
        sb += Wl[k * (2 * D) + D + j] * bias[j];
    }
    g_vr0[k] = s0; g_vr1[k] = s1; g_bvec[k] = sb;
}

// ---------------- generic GEMM: C = epi((A1[+A2]) @ W.T) with W row stride ws --
// BM=64 rows/block, full 128 cols, BK=16. 256 threads: TM=4 x TN=8 register tile.
__global__ __launch_bounds__(256) void gemm_epi(
    const float* __restrict__ A1, const float* __restrict__ A2,
    const float* __restrict__ W, int ws,
    const float* __restrict__ addC, const float* __restrict__ addV,
    float* __restrict__ C, int doRelu, int nrows)
{
    __shared__ float As[16][65];
    __shared__ float Ws[16][128];
    int tid = threadIdx.x;
    int cx = tid & 15;          // col group: cols cx*8 .. +7
    int cy = tid >> 4;          // row group: rows cy*4 .. +3
    int row0 = blockIdx.x * 64;

    float acc[4][8];
#pragma unroll
    for (int r = 0; r < 4; r++)
#pragma unroll
        for (int n = 0; n < 8; n++) acc[r][n] = 0.f;

    int ai = tid >> 2, ak = (tid & 3) * 4;     // A tile loader
    int wc = tid >> 1, wk = (tid & 1) * 8;     // W tile loader
    int ga = row0 + ai;
    bool avalid = ga < nrows;

    for (int kk = 0; kk < 128; kk += 16) {
        float4 av = make_float4(0.f, 0.f, 0.f, 0.f);
        if (avalid) {
            av = *(const float4*)&A1[(size_t)ga * D + kk + ak];
            if (A2) {
                float4 b = *(const float4*)&A2[(size_t)ga * D + kk + ak];
                av.x += b.x; av.y += b.y; av.z += b.z; av.w += b.w;
            }
        }
        As[ak + 0][ai] = av.x; As[ak + 1][ai] = av.y;
        As[ak + 2][ai] = av.z; As[ak + 3][ai] = av.w;

        float4 w0 = *(const float4*)&W[(size_t)wc * ws + kk + wk];
        float4 w1 = *(const float4*)&W[(size_t)wc * ws + kk + wk + 4];
        Ws[wk + 0][wc] = w0.x; Ws[wk + 1][wc] = w0.y;
        Ws[wk + 2][wc] = w0.z; Ws[wk + 3][wc] = w0.w;
        Ws[wk + 4][wc] = w1.x; Ws[wk + 5][wc] = w1.y;
        Ws[wk + 6][wc] = w1.z; Ws[wk + 7][wc] = w1.w;
        __syncthreads();

#pragma unroll
        for (int k = 0; k < 16; k++) {
            float a0 = As[k][cy * 4 + 0], a1 = As[k][cy * 4 + 1];
            float a2 = As[k][cy * 4 + 2], a3 = As[k][cy * 4 + 3];
            float4 b0 = *(const float4*)&Ws[k][cx * 8];
            float4 b1 = *(const float4*)&Ws[k][cx * 8 + 4];
            float bb[8] = {b0.x, b0.y, b0.z, b0.w, b1.x, b1.y, b1.z, b1.w};
#pragma unroll
            for (int n = 0; n < 8; n++) {
                acc[0][n] += a0 * bb[n];
                acc[1][n] += a1 * bb[n];
                acc[2][n] += a2 * bb[n];
                acc[3][n] += a3 * bb[n];
            }
        }
        __syncthreads();
    }

#pragma unroll
    for (int r = 0; r < 4; r++) {
        int gr = row0 + cy * 4 + r;
        if (gr < nrows) {
#pragma unroll
            for (int h = 0; h < 2; h++) {
                int col = cx * 8 + h * 4;
                float4 v = make_float4(acc[r][h * 4 + 0], acc[r][h * 4 + 1],
                                       acc[r][h * 4 + 2], acc[r][h * 4 + 3]);
                if (addC) {
                    float4 c = *(const float4*)&addC[(size_t)gr * D + col];
                    v.x += c.x; v.y += c.y; v.z += c.z; v.w += c.w;
                }
                if (addV) {
                    float4 b = *(const float4*)&addV[col];
                    v.x += b.x; v.y += b.y; v.z += b.z; v.w += b.w;
                }
                if (doRelu) {
                    v.x = fmaxf(v.x, 0.f); v.y = fmaxf(v.y, 0.f);
                    v.z = fmaxf(v.z, 0.f); v.w = fmaxf(v.w, 0.f);
                }
                *(float4*)&C[(size_t)gr * D + col] = v;
            }
        }
    }
}

// ---------------- attention logits (el/er) per node -----------------------------
__global__ __launch_bounds__(256) void scores_net(
    const float* __restrict__ al1, const float* __restrict__ al2,
    const float* __restrict__ ar2) {
    int warp = threadIdx.x >> 5, lane = threadIdx.x & 31;
    int i = blockIdx.x * 8 + warp;
    if (i >= N_NODES) return;
    int o = i * D + lane * 4, c = lane * 4;
    float4 hn = *(const float4*)&g_hnet[o];
    float4 h1 = *(const float4*)&g_hs1[o];
    float4 h2 = *(const float4*)&g_hs2[o];
    float4 v0 = *(const float4*)&g_vr0[c];
    float4 a1 = *(const float4*)&al1[c];
    float4 a2 = *(const float4*)&al2[c];
    float4 r2 = *(const float4*)&ar2[c];
    float d0 = hn.x * v0.x + hn.y * v0.y + hn.z * v0.z + hn.w * v0.w;
    float d1 = h1.x * a1.x + h1.y * a1.y + h1.z * a1.z + h1.w * a1.w;
    float d2 = h2.x * a2.x + h2.y * a2.y + h2.z * a2.z + h2.w * a2.w;
    float d3 = h2.x * r2.x + h2.y * r2.y + h2.z * r2.z + h2.w * r2.w;
#pragma unroll
    for (int off = 16; off; off >>= 1) {
        d0 += __shfl_xor_sync(0xffffffffu, d0, off);
        d1 += __shfl_xor_sync(0xffffffffu, d1, off);
        d2 += __shfl_xor_sync(0xffffffffu, d2, off);
        d3 += __shfl_xor_sync(0xffffffffu, d3, off);
    }
    if (lane == 0) {
        g_er[0][i] = d0;   // er for rel0 (dst=net)
        g_el[1][i] = d1;   // el for rel1 (src=net)
        g_el[2][i] = d2;   // el for rel2
        g_er[2][i] = d3;   // er for rel2 (dst=net, same W)
    }
}

__global__ __launch_bounds__(256) void scores_cell(const float* __restrict__ al0) {
    int warp = threadIdx.x >> 5, lane = threadIdx.x & 31;
    int i = blockIdx.x * 8 + warp;
    if (i >= N_NODES) return;
    int o = i * D + lane * 4, c = lane * 4;
    float4 h0 = *(const float4*)&g_hs0[o];
    float4 hc = *(const float4*)&g_hcell[o];
    float4 a0 = *(const float4*)&al0[c];
    float4 v1 = *(const float4*)&g_vr1[c];
    float d0 = h0.x * a0.x + h0.y * a0.y + h0.z * a0.z + h0.w * a0.w;
    float d1 = hc.x * v1.x + hc.y * v1.y + hc.z * v1.z + hc.w * v1.w;
#pragma unroll
    for (int off = 16; off; off >>= 1) {
        d0 += __shfl_xor_sync(0xffffffffu, d0, off);
        d1 += __shfl_xor_sync(0xffffffffu, d1, off);
    }
    if (lane == 0) {
        g_el[0][i] = d0;   // el for rel0 (src=cell)
        g_er[1][i] = d1;   // er for rel1 (dst=cell)
    }
}

// ---------------- CSR build ------------------------------------------------------
__global__ __launch_bounds__(256) void count_kernel(const int* __restrict__ dst, int rel) {
    int e = blockIdx.x * blockDim.x + threadIdx.x;
    if (e >= N_EDGES) return;
    atomicAdd(&g_cnt[rel][dst[e]], 1);
}

// 256 threads per block, 3 blocks (one per relation). CH = ceil(100000/256) = 391.
__global__ __launch_bounds__(256) void scan_kernel() {
    int r = blockIdx.x;
    const int* cnt = g_cnt[r];
    int* rp = g_rowptr[r];
    __shared__ int part[256];
    int t = threadIdx.x;
    const int CH = 391;  // 256*391 >= 100000
    int base = t * CH;
    int s = 0;
    for (int j = 0; j < CH; j++) {
        int idx = base + j;
        if (idx < N_NODES) s += cnt[idx];
    }
    part[t] = s;
    __syncthreads();
    if (t == 0) {
        int acc = 0;
        for (int i = 0; i < 256; i++) { int v = part[i]; part[i] = acc; acc += v; }
        rp[N_NODES] = acc;
    }
    __syncthreads();
    int acc = part[t];
    for (int j = 0; j < CH; j++) {
        int idx = base + j;
        if (idx < N_NODES) { rp[idx] = acc; acc += cnt[idx]; }
    }
}

__global__ __launch_bounds__(256) void fill_kernel(
    const int* __restrict__ src, const int* __restrict__ dst, int rel) {
    int e = blockIdx.x * blockDim.x + threadIdx.x;
    if (e >= N_EDGES) return;
    int s = src[e], d = dst[e];
    float x = g_el[rel][s] + g_er[rel][d];
    x = x > 0.f ? x : 0.2f * x;           // leaky_relu
    float w = __expf(x);                  // no max-subtraction needed (|x| small)
    int pos = atomicAdd(&g_cursor[rel][d], 1);
    int idx = g_rowptr[rel][d] + pos;
    g_csrc[rel][idx] = s;
    g_cw[rel][idx] = w;
}

// ---------------- atomic-free aggregation: agg[d] = sum(w*hs[src]) / sum(w) -----
__global__ __launch_bounds__(256) void aggregate_kernel(
    const float* __restrict__ hs, float* __restrict__ agg, int rel) {
    int warp = threadIdx.x >> 5, lane = threadIdx.x & 31;
    int i = blockIdx.x * 8 + warp;
    if (i >= N_NODES) return;
    int start = g_rowptr[rel][i];
    int end = g_rowptr[rel][i + 1];
    const float4* hv = (const float4*)hs;
    float4 acc = make_float4(0.f, 0.f, 0.f, 0.f);
    float wsum = 0.f;
    for (int t = start; t < end; t++) {
        int s = g_csrc[rel][t];
        float w = g_cw[rel][t];
        float4 v = hv[(size_t)s * 32 + lane];
        acc.x += w * v.x; acc.y += w * v.y; acc.z += w * v.z; acc.w += w * v.w;
        wsum += w;
    }
    float4 o = make_float4(0.f, 0.f, 0.f, 0.f);
    if (end > start) {
        float inv = 1.f / wsum;
        o = make_float4(acc.x * inv, acc.y * inv, acc.z * inv, acc.w * inv);
    }
    ((float4*)agg)[(size_t)i * 32 + lane] = o;
}

// ---------------- cell step0: out = relu(base_cell + bvec) ----------------------
__global__ __launch_bounds__(256) void cstep0_kernel(float* __restrict__ out) {
    int idx = blockIdx.x * blockDim.x + threadIdx.x;   // over ND/4 float4s
    if (idx >= ND / 4) return;
    float4 b = ((const float4*)g_bcell)[idx];
    int k = (idx & 31) * 4;
    float4 v = *(const float4*)&g_bvec[k];
    float4 r;
    r.x = fmaxf(b.x + v.x, 0.f); r.y = fmaxf(b.y + v.y, 0.f);
    r.z = fmaxf(b.z + v.z, 0.f); r.w = fmaxf(b.w + v.w, 0.f);
    ((float4*)out)[idx] = r;
}

// ---------------- host orchestration --------------------------------------------
extern "C" void kernel_launch(void* const* d_in, const int* in_sizes, int n_in,
                              void* d_out, int out_size) {
    const float* x_net   = (const float*)d_in[0];
    const float* x_cell  = (const float*)d_in[1];
    const float* Wp_net  = (const float*)d_in[2];
    const float* Wp_cell = (const float*)d_in[3];
    const float* Wg0 = (const float*)d_in[4];
    const float* al0 = (const float*)d_in[5];
    const float* ar0 = (const float*)d_in[6];
    const float* Wg1 = (const float*)d_in[7];
    const float* al1 = (const float*)d_in[8];
    const float* ar1 = (const float*)d_in[9];
    const float* Wg2 = (const float*)d_in[10];
    const float* al2 = (const float*)d_in[11];
    const float* ar2 = (const float*)d_in[12];
    const float* Wl   = (const float*)d_in[13];
    const float* bias = (const float*)d_in[14];
    const int* src0 = (const int*)d_in[15];
    const int* dst0 = (const int*)d_in[16];
    const int* src1 = (const int*)d_in[17];
    const int* dst1 = (const int*)d_in[18];
    const int* src2 = (const int*)d_in[19];
    const int* dst2 = (const int*)d_in[20];
    float* out = (float*)d_out;

    float *hnet, *hcell, *hs0, *hs1, *hs2, *bnet, *bcell;
    float *agg0, *agg1, *agg2, *tmpA, *tmpB, *bvec;
    int *cnt, *cursor;
    cudaGetSymbolAddress((void**)&hnet,  g_hnet);
    cudaGetSymbolAddress((void**)&hcell, g_hcell);
    cudaGetSymbolAddress((void**)&hs0,   g_hs0);
    cudaGetSymbolAddress((void**)&hs1,   g_hs1);
    cudaGetSymbolAddress((void**)&hs2,   g_hs2);
    cudaGetSymbolAddress((void**)&bnet,  g_bnet);
    cudaGetSymbolAddress((void**)&bcell, g_bcell);
    cudaGetSymbolAddress((void**)&agg0,  g_agg0);
    cudaGetSymbolAddress((void**)&agg1,  g_agg1);
    cudaGetSymbolAddress((void**)&agg2,  g_agg2);
    cudaGetSymbolAddress((void**)&tmpA,  g_tmpA);
    cudaGetSymbolAddress((void**)&tmpB,  g_tmpB);
    cudaGetSymbolAddress((void**)&bvec,  g_bvec);
    cudaGetSymbolAddress((void**)&cnt,   g_cnt);
    cudaGetSymbolAddress((void**)&cursor, g_cursor);

    cudaMemsetAsync(cnt,    0, sizeof(int) * 3 * N_NODES, 0);
    cudaMemsetAsync(cursor, 0, sizeof(int) * 3 * N_NODES, 0);

    const int GN = (N_NODES + 7) / 8;        // warp-per-node kernels
    const int GG = (N_NODES + 63) / 64;      // gemm tiles
    const int GE = (N_EDGES + 255) / 256;

    // projections + attention vectors
    proj_kernel<<<GN, 256>>>(x_net,  Wp_net,  hnet);
    proj_kernel<<<GN, 256>>>(x_cell, Wp_cell, hcell);
    attnvec_kernel<<<1, D>>>(Wg0, ar0, Wg1, ar1, Wl, bias);

    // h_src per relation + bases
    gemm_epi<<<GG, 256>>>(hcell, nullptr, Wg0, D,     nullptr, nullptr, hs0,  0, N_NODES);
    gemm_epi<<<GG, 256>>>(hnet,  nullptr, Wg1, D,     nullptr, nullptr, hs1,  0, N_NODES);
    gemm_epi<<<GG, 256>>>(hnet,  nullptr, Wg2, D,     nullptr, nullptr, hs2,  0, N_NODES);
    gemm_epi<<<GG, 256>>>(hnet,  nullptr, Wl,  2 * D, nullptr, nullptr, bnet, 0, N_NODES);
    gemm_epi<<<GG, 256>>>(hcell, nullptr, Wl,  2 * D, nullptr, nullptr, bcell, 0, N_NODES);

    // attention logits
    scores_net<<<GN, 256>>>(al1, al2, ar2);
    scores_cell<<<GN, 256>>>(al0);

    // CSR build (count -> scan -> fill with edge weights)
    count_kernel<<<GE, 256>>>(dst0, 0);
    count_kernel<<<GE, 256>>>(dst1, 1);
    count_kernel<<<GE, 256>>>(dst2, 2);
    scan_kernel<<<3, 256>>>();
    fill_kernel<<<GE, 256>>>(src0, dst0, 0);
    fill_kernel<<<GE, 256>>>(src1, dst1, 1);
    fill_kernel<<<GE, 256>>>(src2, dst2, 2);

    // atomic-free softmax-weighted aggregation
    aggregate_kernel<<<GN, 256>>>(hs0, agg0, 0);
    aggregate_kernel<<<GN, 256>>>(hs1, agg1, 1);
    aggregate_kernel<<<GN, 256>>>(hs2, agg2, 2);

    const float* Wl2 = Wl + D;   // Wl[:, 128:], row stride 2*D

    // net chain: 3 wl steps (rel0 adds agg0 at step0, rel2 adds agg2 at step2)
    gemm_epi<<<GG, 256>>>(agg0, nullptr, Wl2, 2 * D, bnet, bvec, tmpA, 1, N_NODES);
    gemm_epi<<<GG, 256>>>(tmpA, nullptr, Wl2, 2 * D, bnet, bvec, tmpB, 1, N_NODES);
    gemm_epi<<<GG, 256>>>(tmpB, agg2,    Wl2, 2 * D, bnet, bvec, out,  1, N_NODES);

    // cell chain: step0 is elementwise (out starts at 0), then 2 wl steps
    cstep0_kernel<<<(ND / 4 + 255) / 256, 256>>>(tmpA);
    gemm_epi<<<GG, 256>>>(tmpA, agg1,    Wl2, 2 * D, bcell, bvec, tmpB, 1, N_NODES);
    gemm_epi<<<GG, 256>>>(tmpB, nullptr, Wl2, 2 * D, bcell, bvec, out + ND, 1, N_NODES);
}

// round 5
// speedup vs baseline: 1.0202x; 1.0202x over previous
#include <cuda_runtime.h>

#define N_NODES 100000
#define N_EDGES 600000
#define D 128
#define DIN 16
#define ND (N_NODES * D)

// ---------------- scratch (static __device__ arrays; no allocs) ----------------
__device__ float g_hnet[ND], g_hcell[ND];                 // projected features
__device__ float g_hs0[ND], g_hs1[ND], g_hs2[ND];         // h_src per relation
__device__ float g_bnet[ND], g_bcell[ND];                 // feat @ Wl1.T
__device__ float g_agg0[ND], g_agg1[ND], g_agg2[ND];      // normalized GAT outputs
__device__ float g_tmpA[ND], g_tmpB[ND];                  // chain intermediates
__device__ float g_el[3][N_NODES], g_er[3][N_NODES];
__device__ float g_vr0[D], g_vr1[D], g_bvec[D];
__device__ int   g_cnt[3][N_NODES];
__device__ int   g_rowptr[3][N_NODES + 1];
__device__ int   g_cursor[3][N_NODES];
__device__ int   g_csrc[3][N_EDGES];
__device__ float g_cw[3][N_EDGES];

// ---------------- feature projection: h = x @ Wp.T  ([N,16] -> [N,128]) --------
__global__ __launch_bounds__(256) void proj_kernel(
    const float* __restrict__ x, const float* __restrict__ Wp,
    float* __restrict__ h) {
    __shared__ float Ws[D * DIN];
    int tid = threadIdx.x;
    for (int i = tid; i < D * DIN; i += 256) Ws[i] = Wp[i];
    __syncthreads();
    int warp = tid >> 5, lane = tid & 31;
    int i = blockIdx.x * 8 + warp;
    if (i >= N_NODES) return;
    float xv = x[i * DIN + (lane & 15)];
    int k0 = lane * 4;
    float acc0 = 0.f, acc1 = 0.f, acc2 = 0.f, acc3 = 0.f;
#pragma unroll
    for (int j = 0; j < 16; j++) {
        float xj = __shfl_sync(0xffffffffu, xv, j);
        acc0 += xj * Ws[(k0 + 0) * 16 + j];
        acc1 += xj * Ws[(k0 + 1) * 16 + j];
        acc2 += xj * Ws[(k0 + 2) * 16 + j];
        acc3 += xj * Ws[(k0 + 3) * 16 + j];
    }
    float4 o = make_float4(acc0, acc1, acc2, acc3);
    *(float4*)&h[i * D + k0] = o;
}

// ---------------- attention vectors: vr0=W0.T@ar0, vr1=W1.T@ar1, bvec=Wl2@bias -
__global__ __launch_bounds__(128) void attnvec_kernel(
    const float* __restrict__ Wg0, const float* __restrict__ ar0,
    const float* __restrict__ Wg1, const float* __restrict__ ar1,
    const float* __restrict__ Wl, const float* __restrict__ bias) {
    int k = threadIdx.x;
    float s0 = 0.f, s1 = 0.f, sb = 0.f;
    for (int j = 0; j < D; j++) {
        s0 += Wg0[j * D + k] * ar0[j];
        s1 += Wg1[j * D + k] * ar1[j];
        sb += Wl[k * (2 * D) + D + j] * bias[j];
    }
    g_vr0[k] = s0; g_vr1[k] = s1; g_bvec[k] = sb;
}

// ---------------- tensor-core GEMM (3xTF32): C = epi((A1[+A2]) @ W.T) ----------
// Tile: M=128 rows/block, N=128 (full), K=128 (full). 256 threads = 8 warps,
// warp grid 4(m) x 2(n): each warp computes 32 rows x 64 cols via m16n8k8 mma.
// 3xTF32 split (hi + lo, drop lo*lo) keeps fp32-level precision.
#define SM_STRIDE 132
#define SMEM_TC (2 * 128 * SM_STRIDE * 4)

__device__ __forceinline__ unsigned f2tf(float x) {
    unsigned r;
    asm("cvt.rna.tf32.f32 %0, %1;" : "=r"(r) : "f"(x));
    return r;
}

#define MMA_TF32(acc, a0, a1, a2, a3, b0, b1)                                   \
    asm volatile(                                                               \
        "mma.sync.aligned.m16n8k8.row.col.f32.tf32.tf32.f32 "                   \
        "{%0,%1,%2,%3},{%4,%5,%6,%7},{%8,%9},{%0,%1,%2,%3};"                    \
        : "+f"(acc[0]), "+f"(acc[1]), "+f"(acc[2]), "+f"(acc[3])                \
        : "r"(a0), "r"(a1), "r"(a2), "r"(a3), "r"(b0), "r"(b1))

__global__ __launch_bounds__(256, 1) void gemm_tc(
    const float* __restrict__ A1, const float* __restrict__ A2,
    const float* __restrict__ W, int ws,
    const float* __restrict__ addC, const float* __restrict__ addV,
    float* __restrict__ C, int doRelu, int nrows)
{
    extern __shared__ float sm[];
    float* As = sm;                       // [128][SM_STRIDE]
    float* Bs = sm + 128 * SM_STRIDE;     // [128][SM_STRIDE] (rows = output col n)
    int tid = threadIdx.x;
    int row0 = blockIdx.x * 128;

    // stage W tile (rows n, K contiguous)
    for (int i = tid; i < 128 * 32; i += 256) {
        int r = i >> 5, c4 = (i & 31) * 4;
        float4 v = *(const float4*)&W[(size_t)r * ws + c4];
        *(float4*)&Bs[r * SM_STRIDE + c4] = v;
    }
    // stage A tile (fp32, with optional A2 add)
    for (int i = tid; i < 128 * 32; i += 256) {
        int r = i >> 5, c4 = (i & 31) * 4;
        int gr = row0 + r;
        float4 v = make_float4(0.f, 0.f, 0.f, 0.f);
        if (gr < nrows) {
            v = *(const float4*)&A1[(size_t)gr * D + c4];
            if (A2) {
                float4 b = *(const float4*)&A2[(size_t)gr * D + c4];
                v.x += b.x; v.y += b.y; v.z += b.z; v.w += b.w;
            }
        }
        *(float4*)&As[r * SM_STRIDE + c4] = v;
    }
    __syncthreads();

    int lane = tid & 31, wid = tid >> 5;
    int wm = wid & 3, wn = wid >> 2;
    int qr = lane >> 2, qc = lane & 3;

    float acc[2][8][4];
#pragma unroll
    for (int mt = 0; mt < 2; mt++)
#pragma unroll
        for (int nt = 0; nt < 8; nt++)
#pragma unroll
            for (int j = 0; j < 4; j++) acc[mt][nt][j] = 0.f;

    for (int k0 = 0; k0 < 128; k0 += 8) {
        unsigned ahi[2][4], alo[2][4];
#pragma unroll
        for (int mt = 0; mt < 2; mt++) {
            int rb = wm * 32 + mt * 16 + qr;
            float x0 = As[rb * SM_STRIDE + k0 + qc];
            float x1 = As[(rb + 8) * SM_STRIDE + k0 + qc];
            float x2 = As[rb * SM_STRIDE + k0 + qc + 4];
            float x3 = As[(rb + 8) * SM_STRIDE + k0 + qc + 4];
            ahi[mt][0] = f2tf(x0); alo[mt][0] = __float_as_uint(x0 - __uint_as_float(ahi[mt][0]));
            ahi[mt][1] = f2tf(x1); alo[mt][1] = __float_as_uint(x1 - __uint_as_float(ahi[mt][1]));
            ahi[mt][2] = f2tf(x2); alo[mt][2] = __float_as_uint(x2 - __uint_as_float(ahi[mt][2]));
            ahi[mt][3] = f2tf(x3); alo[mt][3] = __float_as_uint(x3 - __uint_as_float(ahi[mt][3]));
        }
#pragma unroll
        for (int nt = 0; nt < 8; nt++) {
            int cb = wn * 64 + nt * 8 + qr;
            float y0 = Bs[cb * SM_STRIDE + k0 + qc];
            float y1 = Bs[cb * SM_STRIDE + k0 + qc + 4];
            unsigned bhi0 = f2tf(y0), bhi1 = f2tf(y1);
            unsigned blo0 = __float_as_uint(y0 - __uint_as_float(bhi0));
            unsigned blo1 = __float_as_uint(y1 - __uint_as_float(bhi1));
#pragma unroll
            for (int mt = 0; mt < 2; mt++) {
                MMA_TF32(acc[mt][nt], alo[mt][0], alo[mt][1], alo[mt][2], alo[mt][3], bhi0, bhi1);
                MMA_TF32(acc[mt][nt], ahi[mt][0], ahi[mt][1], ahi[mt][2], ahi[mt][3], blo0, blo1);
                MMA_TF32(acc[mt][nt], ahi[mt][0], ahi[mt][1], ahi[mt][2], ahi[mt][3], bhi0, bhi1);
            }
        }
    }

    // epilogue: c0,c1 at (row, col..col+1), c2,c3 at (row+8, col..col+1)
#pragma unroll
    for (int mt = 0; mt < 2; mt++) {
#pragma unroll
        for (int half = 0; half < 2; half++) {
            int gr = row0 + wm * 32 + mt * 16 + qr + half * 8;
            if (gr >= nrows) continue;
#pragma unroll
            for (int nt = 0; nt < 8; nt++) {
                int col = wn * 64 + nt * 8 + qc * 2;
                float v0 = acc[mt][nt][half * 2 + 0];
                float v1 = acc[mt][nt][half * 2 + 1];
                if (addC) {
                    float2 c = *(const float2*)&addC[(size_t)gr * D + col];
                    v0 += c.x; v1 += c.y;
                }
                if (addV) {
                    float2 b = *(const float2*)&addV[col];
                    v0 += b.x; v1 += b.y;
                }
                if (doRelu) { v0 = fmaxf(v0, 0.f); v1 = fmaxf(v1, 0.f); }
                float2 o = make_float2(v0, v1);
                *(float2*)&C[(size_t)gr * D + col] = o;
            }
        }
    }
}

// ---------------- attention logits (el/er) per node -----------------------------
__global__ __launch_bounds__(256) void scores_net(
    const float* __restrict__ al1, const float* __restrict__ al2,
    const float* __restrict__ ar2) {
    int warp = threadIdx.x >> 5, lane = threadIdx.x & 31;
    int i = blockIdx.x * 8 + warp;
    if (i >= N_NODES) return;
    int o = i * D + lane * 4, c = lane * 4;
    float4 hn = *(const float4*)&g_hnet[o];
    float4 h1 = *(const float4*)&g_hs1[o];
    float4 h2 = *(const float4*)&g_hs2[o];
    float4 v0 = *(const float4*)&g_vr0[c];
    float4 a1 = *(const float4*)&al1[c];
    float4 a2 = *(const float4*)&al2[c];
    float4 r2 = *(const float4*)&ar2[c];
    float d0 = hn.x * v0.x + hn.y * v0.y + hn.z * v0.z + hn.w * v0.w;
    float d1 = h1.x * a1.x + h1.y * a1.y + h1.z * a1.z + h1.w * a1.w;
    float d2 = h2.x * a2.x + h2.y * a2.y + h2.z * a2.z + h2.w * a2.w;
    float d3 = h2.x * r2.x + h2.y * r2.y + h2.z * r2.z + h2.w * r2.w;
#pragma unroll
    for (int off = 16; off; off >>= 1) {
        d0 += __shfl_xor_sync(0xffffffffu, d0, off);
        d1 += __shfl_xor_sync(0xffffffffu, d1, off);
        d2 += __shfl_xor_sync(0xffffffffu, d2, off);
        d3 += __shfl_xor_sync(0xffffffffu, d3, off);
    }
    if (lane == 0) {
        g_er[0][i] = d0;   // er for rel0 (dst=net)
        g_el[1][i] = d1;   // el for rel1 (src=net)
        g_el[2][i] = d2;   // el for rel2
        g_er[2][i] = d3;   // er for rel2 (dst=net, same W)
    }
}

__global__ __launch_bounds__(256) void scores_cell(const float* __restrict__ al0) {
    int warp = threadIdx.x >> 5, lane = threadIdx.x & 31;
    int i = blockIdx.x * 8 + warp;
    if (i >= N_NODES) return;
    int o = i * D + lane * 4, c = lane * 4;
    float4 h0 = *(const float4*)&g_hs0[o];
    float4 hc = *(const float4*)&g_hcell[o];
    float4 a0 = *(const float4*)&al0[c];
    float4 v1 = *(const float4*)&g_vr1[c];
    float d0 = h0.x * a0.x + h0.y * a0.y + h0.z * a0.z + h0.w * a0.w;
    float d1 = hc.x * v1.x + hc.y * v1.y + hc.z * v1.z + hc.w * v1.w;
#pragma unroll
    for (int off = 16; off; off >>= 1) {
        d0 += __shfl_xor_sync(0xffffffffu, d0, off);
        d1 += __shfl_xor_sync(0xffffffffu, d1, off);
    }
    if (lane == 0) {
        g_el[0][i] = d0;   // el for rel0 (src=cell)
        g_er[1][i] = d1;   // er for rel1 (dst=cell)
    }
}

// ---------------- CSR build ------------------------------------------------------
__global__ __launch_bounds__(256) void count3_kernel(
    const int* __restrict__ dst0, const int* __restrict__ dst1,
    const int* __restrict__ dst2) {
    int e = blockIdx.x * blockDim.x + threadIdx.x;
    if (e >= N_EDGES) return;
    atomicAdd(&g_cnt[0][dst0[e]], 1);
    atomicAdd(&g_cnt[1][dst1[e]], 1);
    atomicAdd(&g_cnt[2][dst2[e]], 1);
}

// 256 threads per block, 3 blocks (one per relation). CH = ceil(100000/256) = 391.
__global__ __launch_bounds__(256) void scan_kernel() {
    int r = blockIdx.x;
    const int* cnt = g_cnt[r];
    int* rp = g_rowptr[r];
    __shared__ int part[256];
    int t = threadIdx.x;
    const int CH = 391;  // 256*391 >= 100000
    int base = t * CH;
    int s = 0;
    for (int j = 0; j < CH; j++) {
        int idx = base + j;
        if (idx < N_NODES) s += cnt[idx];
    }
    part[t] = s;
    __syncthreads();
    if (t == 0) {
        int acc = 0;
        for (int i = 0; i < 256; i++) { int v = part[i]; part[i] = acc; acc += v; }
        rp[N_NODES] = acc;
    }
    __syncthreads();
    int acc = part[t];
    for (int j = 0; j < CH; j++) {
        int idx = base + j;
        if (idx < N_NODES) { rp[idx] = acc; acc += cnt[idx]; }
    }
}

__global__ __launch_bounds__(256) void fill_kernel(
    const int* __restrict__ src, const int* __restrict__ dst, int rel) {
    int e = blockIdx.x * blockDim.x + threadIdx.x;
    if (e >= N_EDGES) return;
    int s = src[e], d = dst[e];
    float x = g_el[rel][s] + g_er[rel][d];
    x = x > 0.f ? x : 0.2f * x;           // leaky_relu
    float w = __expf(x);                  // no max-subtraction needed (|x| small)
    int pos = atomicAdd(&g_cursor[rel][d], 1);
    int idx = g_rowptr[rel][d] + pos;
    g_csrc[rel][idx] = s;
    g_cw[rel][idx] = w;
}

// ---------------- atomic-free aggregation (all 3 rels via blockIdx.y) -----------
__global__ __launch_bounds__(256) void aggregate_kernel(
    const float* __restrict__ hsA, const float* __restrict__ hsB,
    const float* __restrict__ hsC,
    float* __restrict__ aggA, float* __restrict__ aggB, float* __restrict__ aggC) {
    int rel = blockIdx.y;
    const float* hs = (rel == 0) ? hsA : (rel == 1) ? hsB : hsC;
    float* agg = (rel == 0) ? aggA : (rel == 1) ? aggB : aggC;
    int warp = threadIdx.x >> 5, lane = threadIdx.x & 31;
    int i = blockIdx.x * 8 + warp;
    if (i >= N_NODES) return;
    int start = g_rowptr[rel][i];
    int end = g_rowptr[rel][i + 1];
    const float4* hv = (const float4*)hs;
    float4 acc = make_float4(0.f, 0.f, 0.f, 0.f);
    float wsum = 0.f;
    for (int t = start; t < end; t++) {
        int s = g_csrc[rel][t];
        float w = g_cw[rel][t];
        float4 v = hv[(size_t)s * 32 + lane];
        acc.x += w * v.x; acc.y += w * v.y; acc.z += w * v.z; acc.w += w * v.w;
        wsum += w;
    }
    float4 o = make_float4(0.f, 0.f, 0.f, 0.f);
    if (end > start) {
        float inv = 1.f / wsum;
        o = make_float4(acc.x * inv, acc.y * inv, acc.z * inv, acc.w * inv);
    }
    ((float4*)agg)[(size_t)i * 32 + lane] = o;
}

// ---------------- cell step0: out = relu(base_cell + bvec) ----------------------
__global__ __launch_bounds__(256) void cstep0_kernel(float* __restrict__ out) {
    int idx = blockIdx.x * blockDim.x + threadIdx.x;   // over ND/4 float4s
    if (idx >= ND / 4) return;
    float4 b = ((const float4*)g_bcell)[idx];
    int k = (idx & 31) * 4;
    float4 v = *(const float4*)&g_bvec[k];
    float4 r;
    r.x = fmaxf(b.x + v.x, 0.f); r.y = fmaxf(b.y + v.y, 0.f);
    r.z = fmaxf(b.z + v.z, 0.f); r.w = fmaxf(b.w + v.w, 0.f);
    ((float4*)out)[idx] = r;
}

// ---------------- host orchestration --------------------------------------------
extern "C" void kernel_launch(void* const* d_in, const int* in_sizes, int n_in,
                              void* d_out, int out_size) {
    const float* x_net   = (const float*)d_in[0];
    const float* x_cell  = (const float*)d_in[1];
    const float* Wp_net  = (const float*)d_in[2];
    const float* Wp_cell = (const float*)d_in[3];
    const float* Wg0 = (const float*)d_in[4];
    const float* al0 = (const float*)d_in[5];
    const float* ar0 = (const float*)d_in[6];
    const float* Wg1 = (const float*)d_in[7];
    const float* al1 = (const float*)d_in[8];
    const float* ar1 = (const float*)d_in[9];
    const float* Wg2 = (const float*)d_in[10];
    const float* al2 = (const float*)d_in[11];
    const float* ar2 = (const float*)d_in[12];
    const float* Wl   = (const float*)d_in[13];
    const float* bias = (const float*)d_in[14];
    const int* src0 = (const int*)d_in[15];
    const int* dst0 = (const int*)d_in[16];
    const int* src1 = (const int*)d_in[17];
    const int* dst1 = (const int*)d_in[18];
    const int* src2 = (const int*)d_in[19];
    const int* dst2 = (const int*)d_in[20];
    float* out = (float*)d_out;

    float *hnet, *hcell, *hs0, *hs1, *hs2, *bnet, *bcell;
    float *agg0, *agg1, *agg2, *tmpA, *tmpB, *bvec;
    int *cnt, *cursor;
    cudaGetSymbolAddress((void**)&hnet,  g_hnet);
    cudaGetSymbolAddress((void**)&hcell, g_hcell);
    cudaGetSymbolAddress((void**)&hs0,   g_hs0);
    cudaGetSymbolAddress((void**)&hs1,   g_hs1);
    cudaGetSymbolAddress((void**)&hs2,   g_hs2);
    cudaGetSymbolAddress((void**)&bnet,  g_bnet);
    cudaGetSymbolAddress((void**)&bcell, g_bcell);
    cudaGetSymbolAddress((void**)&agg0,  g_agg0);
    cudaGetSymbolAddress((void**)&agg1,  g_agg1);
    cudaGetSymbolAddress((void**)&agg2,  g_agg2);
    cudaGetSymbolAddress((void**)&tmpA,  g_tmpA);
    cudaGetSymbolAddress((void**)&tmpB,  g_tmpB);
    cudaGetSymbolAddress((void**)&bvec,  g_bvec);
    cudaGetSymbolAddress((void**)&cnt,   g_cnt);
    cudaGetSymbolAddress((void**)&cursor, g_cursor);

    static int smem_set = 0;
    if (!smem_set) {
        cudaFuncSetAttribute(gemm_tc, cudaFuncAttributeMaxDynamicSharedMemorySize, SMEM_TC);
        smem_set = 1;
    }

    cudaMemsetAsync(cnt,    0, sizeof(int) * 3 * N_NODES, 0);
    cudaMemsetAsync(cursor, 0, sizeof(int) * 3 * N_NODES, 0);

    const int GN = (N_NODES + 7) / 8;        // warp-per-node kernels
    const int GT = (N_NODES + 127) / 128;    // tensor gemm tiles
    const int GE = (N_EDGES + 255) / 256;

    // projections + attention vectors
    proj_kernel<<<GN, 256>>>(x_net,  Wp_net,  hnet);
    proj_kernel<<<GN, 256>>>(x_cell, Wp_cell, hcell);
    attnvec_kernel<<<1, D>>>(Wg0, ar0, Wg1, ar1, Wl, bias);

    // h_src per relation + bases (tensor-core 3xTF32)
    gemm_tc<<<GT, 256, SMEM_TC>>>(hcell, nullptr, Wg0, D,     nullptr, nullptr, hs0,  0, N_NODES);
    gemm_tc<<<GT, 256, SMEM_TC>>>(hnet,  nullptr, Wg1, D,     nullptr, nullptr, hs1,  0, N_NODES);
    gemm_tc<<<GT, 256, SMEM_TC>>>(hnet,  nullptr, Wg2, D,     nullptr, nullptr, hs2,  0, N_NODES);
    gemm_tc<<<GT, 256, SMEM_TC>>>(hnet,  nullptr, Wl,  2 * D, nullptr, nullptr, bnet, 0, N_NODES);
    gemm_tc<<<GT, 256, SMEM_TC>>>(hcell, nullptr, Wl,  2 * D, nullptr, nullptr, bcell, 0, N_NODES);

    // attention logits
    scores_net<<<GN, 256>>>(al1, al2, ar2);
    scores_cell<<<GN, 256>>>(al0);

    // CSR build (count -> scan -> fill with edge weights)
    count3_kernel<<<GE, 256>>>(dst0, dst1, dst2);
    scan_kernel<<<3, 256>>>();
    fill_kernel<<<GE, 256>>>(src0, dst0, 0);
    fill_kernel<<<GE, 256>>>(src1, dst1, 1);
    fill_kernel<<<GE, 256>>>(src2, dst2, 2);

    // atomic-free softmax-weighted aggregation (3 rels in one launch)
    dim3 gagg(GN, 3);
    aggregate_kernel<<<gagg, 256>>>(hs0, hs1, hs2, agg0, agg1, agg2);

    const float* Wl2 = Wl + D;   // Wl[:, 128:], row stride 2*D

    // net chain: 3 wl steps (rel0 adds agg0 at step0, rel2 adds agg2 at step2)
    gemm_tc<<<GT, 256, SMEM_TC>>>(agg0, nullptr, Wl2, 2 * D, bnet, bvec, tmpA, 1, N_NODES);
    gemm_tc<<<GT, 256, SMEM_TC>>>(tmpA, nullptr, Wl2, 2 * D, bnet, bvec, tmpB, 1, N_NODES);
    gemm_tc<<<GT, 256, SMEM_TC>>>(tmpB, agg2,    Wl2, 2 * D, bnet, bvec, out,  1, N_NODES);

    // cell chain: step0 is elementwise (out starts at 0), then 2 wl steps
    cstep0_kernel<<<(ND / 4 + 255) / 256, 256>>>(tmpA);
    gemm_tc<<<GT, 256, SMEM_TC>>>(tmpA, agg1,    Wl2, 2 * D, bcell, bvec, tmpB, 1, N_NODES);
    gemm_tc<<<GT, 256, SMEM_TC>>>(tmpB, nullptr, Wl2, 2 * D, bcell, bvec, out + ND, 1, N_NODES);
}

// round 7
// speedup vs baseline: 1.3049x; 1.2792x over previous
#include <cuda_runtime.h>

#define N_NODES 100000
#define N_EDGES 600000
#define D 128
#define DIN 16
#define ND (N_NODES * D)

// ---------------- scratch (static __device__ arrays; no allocs) ----------------
__device__ float g_hnet[ND], g_hcell[ND];                 // projected features
__device__ float g_hs0[ND], g_hs1[ND], g_hs2[ND];         // h_src per relation
__device__ float g_bnet[ND], g_bcell[ND];                 // feat @ Wl1.T
__device__ float g_agg0[ND], g_agg1[ND], g_agg2[ND];      // normalized GAT outputs
__device__ float g_tmpA[ND], g_tmpB[ND];                  // net chain intermediates
__device__ float g_tmpC[ND], g_tmpD[ND];                  // cell chain intermediates
__device__ float g_el[3][N_NODES], g_er[3][N_NODES];
__device__ float g_vr0[D], g_vr1[D], g_bvec[D];
__device__ int   g_cnt[3][N_NODES];
__device__ int   g_rowptr[3][N_NODES + 1];
__device__ int   g_cursor[3][N_NODES];
__device__ int   g_csrc[3][N_EDGES];
__device__ float g_cw[3][N_EDGES];

// ---------------- feature projection: h = x @ Wp.T  ([N,16] -> [N,128]) --------
__global__ __launch_bounds__(256) void proj_kernel(
    const float* __restrict__ x, const float* __restrict__ Wp,
    float* __restrict__ h) {
    __shared__ float Ws[D * DIN];
    int tid = threadIdx.x;
    for (int i = tid; i < D * DIN; i += 256) Ws[i] = Wp[i];
    __syncthreads();
    int warp = tid >> 5, lane = tid & 31;
    int i = blockIdx.x * 8 + warp;
    if (i >= N_NODES) return;
    float xv = x[i * DIN + (lane & 15)];
    int k0 = lane * 4;
    float acc0 = 0.f, acc1 = 0.f, acc2 = 0.f, acc3 = 0.f;
#pragma unroll
    for (int j = 0; j < 16; j++) {
        float xj = __shfl_sync(0xffffffffu, xv, j);
        acc0 += xj * Ws[(k0 + 0) * 16 + j];
        acc1 += xj * Ws[(k0 + 1) * 16 + j];
        acc2 += xj * Ws[(k0 + 2) * 16 + j];
        acc3 += xj * Ws[(k0 + 3) * 16 + j];
    }
    float4 o = make_float4(acc0, acc1, acc2, acc3);
    *(float4*)&h[i * D + k0] = o;
}

// ---------------- attention vectors: vr0=W0.T@ar0, vr1=W1.T@ar1, bvec=Wl2@bias -
__global__ __launch_bounds__(128) void attnvec_kernel(
    const float* __restrict__ Wg0, const float* __restrict__ ar0,
    const float* __restrict__ Wg1, const float* __restrict__ ar1,
    const float* __restrict__ Wl, const float* __restrict__ bias) {
    int k = threadIdx.x;
    float s0 = 0.f, s1 = 0.f, sb = 0.f;
    for (int j = 0; j < D; j++) {
        s0 += Wg0[j * D + k] * ar0[j];
        s1 += Wg1[j * D + k] * ar1[j];
        sb += Wl[k * (2 * D) + D + j] * bias[j];
    }
    g_vr0[k] = s0; g_vr1[k] = s1; g_bvec[k] = sb;
}

// ---------------- tensor-core GEMM (3xTF32): C = epi((A1[+A2]) @ W.T) ----------
// Tile: M=64 rows/block, N=128, K=128. 256 threads = 8 warps in 2(m) x 4(n) grid;
// each warp computes 32 rows x 32 cols via m16n8k8 mma (2 mt x 4 nt).
// smem = 64*132*4 + 128*132*4 = 101.4KB -> 2 CTAs/SM (16 warps resident).
#define SM_STRIDE 132
#define SMEM_TC ((64 + 128) * SM_STRIDE * 4)

__device__ __forceinline__ unsigned f2tf(float x) {
    unsigned r;
    asm("cvt.rna.tf32.f32 %0, %1;" : "=r"(r) : "f"(x));
    return r;
}

#define MMA_TF32(acc, a0, a1, a2, a3, b0, b1)                                   \
    asm volatile(                                                               \
        "mma.sync.aligned.m16n8k8.row.col.f32.tf32.tf32.f32 "                   \
        "{%0,%1,%2,%3},{%4,%5,%6,%7},{%8,%9},{%0,%1,%2,%3};"                    \
        : "+f"(acc[0]), "+f"(acc[1]), "+f"(acc[2]), "+f"(acc[3])                \
        : "r"(a0), "r"(a1), "r"(a2), "r"(a3), "r"(b0), "r"(b1))

__global__ __launch_bounds__(256, 2) void gemm_tc(
    const float* __restrict__ A1, const float* __restrict__ A2,
    const float* __restrict__ W, int ws,
    const float* __restrict__ addC, const float* __restrict__ addV,
    float* __restrict__ C, int doRelu, int nrows)
{
    extern __shared__ float sm[];
    float* As = sm;                       // [64][SM_STRIDE]
    float* Bs = sm + 64 * SM_STRIDE;      // [128][SM_STRIDE] (rows = output col n)
    int tid = threadIdx.x;
    int row0 = blockIdx.x * 64;

    // stage W tile (rows n, K contiguous)
    for (int i = tid; i < 128 * 32; i += 256) {
        int r = i >> 5, c4 = (i & 31) * 4;
        float4 v = *(const float4*)&W[(size_t)r * ws + c4];
        *(float4*)&Bs[r * SM_STRIDE + c4] = v;
    }
    // stage A tile (fp32, with optional A2 add)
    for (int i = tid; i < 64 * 32; i += 256) {
        int r = i >> 5, c4 = (i & 31) * 4;
        int gr = row0 + r;
        float4 v = make_float4(0.f, 0.f, 0.f, 0.f);
        if (gr < nrows) {
            v = *(const float4*)&A1[(size_t)gr * D + c4];
            if (A2) {
                float4 b = *(const float4*)&A2[(size_t)gr * D + c4];
                v.x += b.x; v.y += b.y; v.z += b.z; v.w += b.w;
            }
        }
        *(float4*)&As[r * SM_STRIDE + c4] = v;
    }
    __syncthreads();

    int lane = tid & 31, wid = tid >> 5;
    int wm = wid & 1, wn = wid >> 1;          // 2 x 4 warp grid
    int qr = lane >> 2, qc = lane & 3;

    float acc[2][4][4];
#pragma unroll
    for (int mt = 0; mt < 2; mt++)
#pragma unroll
        for (int nt = 0; nt < 4; nt++)
#pragma unroll
            for (int j = 0; j < 4; j++) acc[mt][nt][j] = 0.f;

    for (int k0 = 0; k0 < 128; k0 += 8) {
        unsigned ahi[2][4], alo[2][4];
#pragma unroll
        for (int mt = 0; mt < 2; mt++) {
            int rb = wm * 32 + mt * 16 + qr;
            float x0 = As[rb * SM_STRIDE + k0 + qc];
            float x1 = As[(rb + 8) * SM_STRIDE + k0 + qc];
            float x2 = As[rb * SM_STRIDE + k0 + qc + 4];
            float x3 = As[(rb + 8) * SM_STRIDE + k0 + qc + 4];
            ahi[mt][0] = f2tf(x0); alo[mt][0] = __float_as_uint(x0 - __uint_as_float(ahi[mt][0]));
            ahi[mt][1] = f2tf(x1); alo[mt][1] = __float_as_uint(x1 - __uint_as_float(ahi[mt][1]));
            ahi[mt][2] = f2tf(x2); alo[mt][2] = __float_as_uint(x2 - __uint_as_float(ahi[mt][2]));
            ahi[mt][3] = f2tf(x3); alo[mt][3] = __float_as_uint(x3 - __uint_as_float(ahi[mt][3]));
        }
#pragma unroll
        for (int nt = 0; nt < 4; nt++) {
            int cb = wn * 32 + nt * 8 + qr;
            float y0 = Bs[cb * SM_STRIDE + k0 + qc];
            float y1 = Bs[cb * SM_STRIDE + k0 + qc + 4];
            unsigned bhi0 = f2tf(y0), bhi1 = f2tf(y1);
            unsigned blo0 = __float_as_uint(y0 - __uint_as_float(bhi0));
            unsigned blo1 = __float_as_uint(y1 - __uint_as_float(bhi1));
#pragma unroll
            for (int mt = 0; mt < 2; mt++) {
                MMA_TF32(acc[mt][nt], alo[mt][0], alo[mt][1], alo[mt][2], alo[mt][3], bhi0, bhi1);
                MMA_TF32(acc[mt][nt], ahi[mt][0], ahi[mt][1], ahi[mt][2], ahi[mt][3], blo0, blo1);
                MMA_TF32(acc[mt][nt], ahi[mt][0], ahi[mt][1], ahi[mt][2], ahi[mt][3], bhi0, bhi1);
            }
        }
    }

    // epilogue
#pragma unroll
    for (int mt = 0; mt < 2; mt++) {
#pragma unroll
        for (int half = 0; half < 2; half++) {
            int gr = row0 + wm * 32 + mt * 16 + qr + half * 8;
            if (gr >= nrows) continue;
#pragma unroll
            for (int nt = 0; nt < 4; nt++) {
                int col = wn * 32 + nt * 8 + qc * 2;
                float v0 = acc[mt][nt][half * 2 + 0];
                float v1 = acc[mt][nt][half * 2 + 1];
                if (addC) {
                    float2 c = *(const float2*)&addC[(size_t)gr * D + col];
                    v0 += c.x; v1 += c.y;
                }
                if (addV) {
                    float2 b = *(const float2*)&addV[col];
                    v0 += b.x; v1 += b.y;
                }
                if (doRelu) { v0 = fmaxf(v0, 0.f); v1 = fmaxf(v1, 0.f); }
                float2 o = make_float2(v0, v1);
                *(float2*)&C[(size_t)gr * D + col] = o;
            }
        }
    }
}

// ---------------- attention logits (el/er) per node -----------------------------
__global__ __launch_bounds__(256) void scores_net(
    const float* __restrict__ al1, const float* __restrict__ al2,
    const float* __restrict__ ar2) {
    int warp = threadIdx.x >> 5, lane = threadIdx.x & 31;
    int i = blockIdx.x * 8 + warp;
    if (i >= N_NODES) return;
    int o = i * D + lane * 4, c = lane * 4;
    float4 hn = *(const float4*)&g_hnet[o];
    float4 h1 = *(const float4*)&g_hs1[o];
    float4 h2 = *(const float4*)&g_hs2[o];
    float4 v0 = *(const float4*)&g_vr0[c];
    float4 a1 = *(const float4*)&al1[c];
    float4 a2 = *(const float4*)&al2[c];
    float4 r2 = *(const float4*)&ar2[c];
    float d0 = hn.x * v0.x + hn.y * v0.y + hn.z * v0.z + hn.w * v0.w;
    float d1 = h1.x * a1.x + h1.y * a1.y + h1.z * a1.z + h1.w * a1.w;
    float d2 = h2.x * a2.x + h2.y * a2.y + h2.z * a2.z + h2.w * a2.w;
    float d3 = h2.x * r2.x + h2.y * r2.y + h2.z * r2.z + h2.w * r2.w;
#pragma unroll
    for (int off = 16; off; off >>= 1) {
        d0 += __shfl_xor_sync(0xffffffffu, d0, off);
        d1 += __shfl_xor_sync(0xffffffffu, d1, off);
        d2 += __shfl_xor_sync(0xffffffffu, d2, off);
        d3 += __shfl_xor_sync(0xffffffffu, d3, off);
    }
    if (lane == 0) {
        g_er[0][i] = d0;   // er for rel0 (dst=net)
        g_el[1][i] = d1;   // el for rel1 (src=net)
        g_el[2][i] = d2;   // el for rel2
        g_er[2][i] = d3;   // er for rel2 (dst=net, same W)
    }
}

__global__ __launch_bounds__(256) void scores_cell(const float* __restrict__ al0) {
    int warp = threadIdx.x >> 5, lane = threadIdx.x & 31;
    int i = blockIdx.x * 8 + warp;
    if (i >= N_NODES) return;
    int o = i * D + lane * 4, c = lane * 4;
    float4 h0 = *(const float4*)&g_hs0[o];
    float4 hc = *(const float4*)&g_hcell[o];
    float4 a0 = *(const float4*)&al0[c];
    float4 v1 = *(const float4*)&g_vr1[c];
    float d0 = h0.x * a0.x + h0.y * a0.y + h0.z * a0.z + h0.w * a0.w;
    float d1 = hc.x * v1.x + hc.y * v1.y + hc.z * v1.z + hc.w * v1.w;
#pragma unroll
    for (int off = 16; off; off >>= 1) {
        d0 += __shfl_xor_sync(0xffffffffu, d0, off);
        d1 += __shfl_xor_sync(0xffffffffu, d1, off);
    }
    if (lane == 0) {
        g_el[0][i] = d0;   // el for rel0 (src=cell)
        g_er[1][i] = d1;   // er for rel1 (dst=cell)
    }
}

// ---------------- CSR build ------------------------------------------------------
__global__ __launch_bounds__(256) void count3_kernel(
    const int* __restrict__ dst0, const int* __restrict__ dst1,
    const int* __restrict__ dst2) {
    int e = blockIdx.x * blockDim.x + threadIdx.x;
    if (e >= N_EDGES) return;
    atomicAdd(&g_cnt[0][dst0[e]], 1);
    atomicAdd(&g_cnt[1][dst1[e]], 1);
    atomicAdd(&g_cnt[2][dst2[e]], 1);
}

__global__ __launch_bounds__(256) void scan_kernel() {
    int r = blockIdx.x;
    const int* cnt = g_cnt[r];
    int* rp = g_rowptr[r];
    __shared__ int part[256];
    int t = threadIdx.x;
    const int CH = 391;  // 256*391 >= 100000
    int base = t * CH;
    int s = 0;
    for (int j = 0; j < CH; j++) {
        int idx = base + j;
        if (idx < N_NODES) s += cnt[idx];
    }
    part[t] = s;
    __syncthreads();
    if (t == 0) {
        int acc = 0;
        for (int i = 0; i < 256; i++) { int v = part[i]; part[i] = acc; acc += v; }
        rp[N_NODES] = acc;
    }
    __syncthreads();
    int acc = part[t];
    for (int j = 0; j < CH; j++) {
        int idx = base + j;
        if (idx < N_NODES) { rp[idx] = acc; acc += cnt[idx]; }
    }
}

__global__ __launch_bounds__(256) void fill_kernel(
    const int* __restrict__ src, const int* __restrict__ dst, int rel) {
    int e = blockIdx.x * blockDim.x + threadIdx.x;
    if (e >= N_EDGES) return;
    int s = src[e], d = dst[e];
    float x = g_el[rel][s] + g_er[rel][d];
    x = x > 0.f ? x : 0.2f * x;           // leaky_relu
    float w = __expf(x);                  // no max-subtraction needed (|x| small)
    int pos = atomicAdd(&g_cursor[rel][d], 1);
    int idx = g_rowptr[rel][d] + pos;
    g_csrc[rel][idx] = s;
    g_cw[rel][idx] = w;
}

// ---------------- atomic-free aggregation: agg[d] = sum(w*hs[src]) / sum(w) -----
__global__ __launch_bounds__(256) void aggregate_kernel(
    const float* __restrict__ hs, float* __restrict__ agg, int rel) {
    int warp = threadIdx.x >> 5, lane = threadIdx.x & 31;
    int i = blockIdx.x * 8 + warp;
    if (i >= N_NODES) return;
    int start = g_rowptr[rel][i];
    int end = g_rowptr[rel][i + 1];
    const float4* hv = (const float4*)hs;
    float4 acc = make_float4(0.f, 0.f, 0.f, 0.f);
    float wsum = 0.f;
    for (int t = start; t < end; t++) {
        int s = g_csrc[rel][t];
        float w = g_cw[rel][t];
        float4 v = hv[(size_t)s * 32 + lane];
        acc.x += w * v.x; acc.y += w * v.y; acc.z += w * v.z; acc.w += w * v.w;
        wsum += w;
    }
    float4 o = make_float4(0.f, 0.f, 0.f, 0.f);
    if (end > start) {
        float inv = 1.f / wsum;
        o = make_float4(acc.x * inv, acc.y * inv, acc.z * inv, acc.w * inv);
    }
    ((float4*)agg)[(size_t)i * 32 + lane] = o;
}

// ---------------- cell step0: out = relu(base_cell + bvec) ----------------------
__global__ __launch_bounds__(256) void cstep0_kernel(float* __restrict__ out) {
    int idx = blockIdx.x * blockDim.x + threadIdx.x;   // over ND/4 float4s
    if (idx >= ND / 4) return;
    float4 b = ((const float4*)g_bcell)[idx];
    int k = (idx & 31) * 4;
    float4 v = *(const float4*)&g_bvec[k];
    float4 r;
    r.x = fmaxf(b.x + v.x, 0.f); r.y = fmaxf(b.y + v.y, 0.f);
    r.z = fmaxf(b.z + v.z, 0.f); r.w = fmaxf(b.w + v.w, 0.f);
    ((float4*)out)[idx] = r;
}

// ---------------- host orchestration (3-stream fork/join DAG) -------------------
extern "C" void kernel_launch(void* const* d_in, const int* in_sizes, int n_in,
                              void* d_out, int out_size) {
    const float* x_net   = (const float*)d_in[0];
    const float* x_cell  = (const float*)d_in[1];
    const float* Wp_net  = (const float*)d_in[2];
    const float* Wp_cell = (const float*)d_in[3];
    const float* Wg0 = (const float*)d_in[4];
    const float* al0 = (const float*)d_in[5];
    const float* ar0 = (const float*)d_in[6];
    const float* Wg1 = (const float*)d_in[7];
    const float* al1 = (const float*)d_in[8];
    const float* ar1 = (const float*)d_in[9];
    const float* Wg2 = (const float*)d_in[10];
    const float* al2 = (const float*)d_in[11];
    const float* ar2 = (const float*)d_in[12];
    const float* Wl   = (const float*)d_in[13];
    const float* bias = (const float*)d_in[14];
    const int* src0 = (const int*)d_in[15];
    const int* dst0 = (const int*)d_in[16];
    const int* src1 = (const int*)d_in[17];
    const int* dst1 = (const int*)d_in[18];
    const int* src2 = (const int*)d_in[19];
    const int* dst2 = (const int*)d_in[20];
    float* out = (float*)d_out;

    float *hnet, *hcell, *hs0, *hs1, *hs2, *bnet, *bcell;
    float *agg0, *agg1, *agg2, *tmpA, *tmpB, *tmpC, *tmpD, *bvec;
    int *cnt, *cursor;
    cudaGetSymbolAddress((void**)&hnet,  g_hnet);
    cudaGetSymbolAddress((void**)&hcell, g_hcell);
    cudaGetSymbolAddress((void**)&hs0,   g_hs0);
    cudaGetSymbolAddress((void**)&hs1,   g_hs1);
    cudaGetSymbolAddress((void**)&hs2,   g_hs2);
    cudaGetSymbolAddress((void**)&bnet,  g_bnet);
    cudaGetSymbolAddress((void**)&bcell, g_bcell);
    cudaGetSymbolAddress((void**)&agg0,  g_agg0);
    cudaGetSymbolAddress((void**)&agg1,  g_agg1);
    cudaGetSymbolAddress((void**)&agg2,  g_agg2);
    cudaGetSymbolAddress((void**)&tmpA,  g_tmpA);
    cudaGetSymbolAddress((void**)&tmpB,  g_tmpB);
    cudaGetSymbolAddress((void**)&tmpC,  g_tmpC);
    cudaGetSymbolAddress((void**)&tmpD,  g_tmpD);
    cudaGetSymbolAddress((void**)&bvec,  g_bvec);
    cudaGetSymbolAddress((void**)&cnt,   g_cnt);
    cudaGetSymbolAddress((void**)&cursor, g_cursor);

    static cudaStream_t sA = 0, sB = 0, sC = 0;
    static cudaEvent_t evFork, eA1, eB1, eC1, eC2, eA3, eB3;
    static int init_done = 0;
    if (!init_done) {
        cudaFuncSetAttribute(gemm_tc, cudaFuncAttributeMaxDynamicSharedMemorySize, SMEM_TC);
        cudaStreamCreateWithFlags(&sA, cudaStreamNonBlocking);
        cudaStreamCreateWithFlags(&sB, cudaStreamNonBlocking);
        cudaStreamCreateWithFlags(&sC, cudaStreamNonBlocking);
        cudaEventCreateWithFlags(&evFork, cudaEventDisableTiming);
        cudaEventCreateWithFlags(&eA1, cudaEventDisableTiming);
        cudaEventCreateWithFlags(&eB1, cudaEventDisableTiming);
        cudaEventCreateWithFlags(&eC1, cudaEventDisableTiming);
        cudaEventCreateWithFlags(&eC2, cudaEventDisableTiming);
        cudaEventCreateWithFlags(&eA3, cudaEventDisableTiming);
        cudaEventCreateWithFlags(&eB3, cudaEventDisableTiming);
        init_done = 1;
    }

    const int GN = (N_NODES + 7) / 8;        // warp-per-node kernels
    const int GT = (N_NODES + 63) / 64;      // tensor gemm tiles (BM=64)
    const int GE = (N_EDGES + 255) / 256;
    const float* Wl2 = Wl + D;               // Wl[:, 128:], row stride 2*D

    // ---- pre-fork (origin stream): tiny attention-vector GEMVs ----
    attnvec_kernel<<<1, D, 0, 0>>>(Wg0, ar0, Wg1, ar1, Wl, bias);
    cudaEventRecord(evFork, 0);
    cudaStreamWaitEvent(sA, evFork, 0);
    cudaStreamWaitEvent(sB, evFork, 0);
    cudaStreamWaitEvent(sC, evFork, 0);

    // ---- branch C: CSR skeleton (independent of features) ----
    cudaMemsetAsync(cnt,    0, sizeof(int) * 3 * N_NODES, sC);
    cudaMemsetAsync(cursor, 0, sizeof(int) * 3 * N_NODES, sC);
    count3_kernel<<<GE, 256, 0, sC>>>(dst0, dst1, dst2);
    scan_kernel<<<3, 256, 0, sC>>>();
    cudaEventRecord(eC1, sC);

    // ---- branch A: net-side features ----
    proj_kernel<<<GN, 256, 0, sA>>>(x_net, Wp_net, hnet);
    gemm_tc<<<GT, 256, SMEM_TC, sA>>>(hnet, nullptr, Wg1, D,     nullptr, nullptr, hs1,  0, N_NODES);
    gemm_tc<<<GT, 256, SMEM_TC, sA>>>(hnet, nullptr, Wg2, D,     nullptr, nullptr, hs2,  0, N_NODES);
    gemm_tc<<<GT, 256, SMEM_TC, sA>>>(hnet, nullptr, Wl,  2 * D, nullptr, nullptr, bnet, 0, N_NODES);
    scores_net<<<GN, 256, 0, sA>>>(al1, al2, ar2);
    cudaEventRecord(eA1, sA);

    // ---- branch B: cell-side features ----
    proj_kernel<<<GN, 256, 0, sB>>>(x_cell, Wp_cell, hcell);
    gemm_tc<<<GT, 256, SMEM_TC, sB>>>(hcell, nullptr, Wg0, D,     nullptr, nullptr, hs0,  0, N_NODES);
    gemm_tc<<<GT, 256, SMEM_TC, sB>>>(hcell, nullptr, Wl,  2 * D, nullptr, nullptr, bcell, 0, N_NODES);
    scores_cell<<<GN, 256, 0, sB>>>(al0);
    cudaEventRecord(eB1, sB);

    // ---- join J1: scores + CSR skeleton complete everywhere ----
    cudaStreamWaitEvent(sA, eB1, 0); cudaStreamWaitEvent(sA, eC1, 0);
    cudaStreamWaitEvent(sB, eA1, 0); cudaStreamWaitEvent(sB, eC1, 0);
    cudaStreamWaitEvent(sC, eA1, 0); cudaStreamWaitEvent(sC, eB1, 0);

    // ---- per-relation fill + aggregate, one relation per stream ----
    fill_kernel<<<GE, 256, 0, sA>>>(src0, dst0, 0);
    aggregate_kernel<<<GN, 256, 0, sA>>>(hs0, agg0, 0);
    fill_kernel<<<GE, 256, 0, sB>>>(src1, dst1, 1);
    aggregate_kernel<<<GN, 256, 0, sB>>>(hs1, agg1, 1);
    fill_kernel<<<GE, 256, 0, sC>>>(src2, dst2, 2);
    aggregate_kernel<<<GN, 256, 0, sC>>>(hs2, agg2, 2);
    cudaEventRecord(eC2, sC);

    // ---- branch A: net output chain (needs agg0 local, agg2 from C) ----
    gemm_tc<<<GT, 256, SMEM_TC, sA>>>(agg0, nullptr, Wl2, 2 * D, bnet, bvec, tmpA, 1, N_NODES);
    gemm_tc<<<GT, 256, SMEM_TC, sA>>>(tmpA, nullptr, Wl2, 2 * D, bnet, bvec, tmpB, 1, N_NODES);
    cudaStreamWaitEvent(sA, eC2, 0);
    gemm_tc<<<GT, 256, SMEM_TC, sA>>>(tmpB, agg2,    Wl2, 2 * D, bnet, bvec, out,  1, N_NODES);
    cudaEventRecord(eA3, sA);

    // ---- branch B: cell output chain (agg1 local) ----
    cstep0_kernel<<<(ND / 4 + 255) / 256, 256, 0, sB>>>(tmpC);
    gemm_tc<<<GT, 256, SMEM_TC, sB>>>(tmpC, agg1,    Wl2, 2 * D, bcell, bvec, tmpD, 1, N_NODES);
    gemm_tc<<<GT, 256, SMEM_TC, sB>>>(tmpD, nullptr, Wl2, 2 * D, bcell, bvec, out + ND, 1, N_NODES);
    cudaEventRecord(eB3, sB);

    // ---- join back to origin stream ----
    cudaStreamWaitEvent(0, eA3, 0);
    cudaStreamWaitEvent(0, eB3, 0);
}

// round 8
// speedup vs baseline: 1.4932x; 1.1442x over previous
#include <cuda_runtime.h>

#define N_NODES 100000
#define N_EDGES 600000
#define D 128
#define DIN 16
#define ND (N_NODES * D)

// ---------------- scratch (static __device__ arrays; no allocs) ----------------
__device__ float g_hnet[ND], g_hcell[ND];                 // projected features
__device__ float g_hs0[ND], g_hs1[ND], g_hs2[ND];         // h_src per relation
__device__ float g_bnet[ND], g_bcell[ND];                 // feat @ Wl1.T
__device__ float g_agg0[ND], g_agg1[ND], g_agg2[ND];      // normalized GAT outputs
__device__ float g_tmpA[ND], g_tmpB[ND];                  // net chain intermediates
__device__ float g_tmpC[ND], g_tmpD[ND];                  // cell chain intermediates
__device__ float g_el[3][N_NODES], g_er[3][N_NODES];
__device__ float g_vr0[D], g_vr1[D], g_bvec[D];
__device__ int   g_cnt[3][N_NODES];
__device__ int   g_rowptr[3][N_NODES + 1];
__device__ int   g_cursor[3][N_NODES];
__device__ int   g_csrc[3][N_EDGES];
__device__ float g_cw[3][N_EDGES];

// ---------------- feature projection: h = x @ Wp.T  ([N,16] -> [N,128]) --------
// W staged TRANSPOSED in smem; inner loop reads float4 at Wt[j][lane*4]
// (16B lane stride -> conflict-free LDS.128), replacing the old 32-way-conflicted
// scalar reads.
__global__ __launch_bounds__(256) void proj_kernel(
    const float* __restrict__ x, const float* __restrict__ Wp,
    float* __restrict__ h) {
    __shared__ float Wt[DIN][D];          // Wt[j][k] = Wp[k][j]
    int tid = threadIdx.x;
    for (int i = tid; i < D * DIN; i += 256) {
        int k = i >> 4, j = i & 15;       // Wp row k, col j
        Wt[j][k] = Wp[i];
    }
    __syncthreads();
    int warp = tid >> 5, lane = tid & 31;
    int i = blockIdx.x * 8 + warp;
    if (i >= N_NODES) return;
    float xv = x[i * DIN + (lane & 15)];
    int k0 = lane * 4;
    float4 acc = make_float4(0.f, 0.f, 0.f, 0.f);
#pragma unroll
    for (int j = 0; j < 16; j++) {
        float xj = __shfl_sync(0xffffffffu, xv, j);
        float4 w = *(const float4*)&Wt[j][k0];
        acc.x += xj * w.x; acc.y += xj * w.y;
        acc.z += xj * w.z; acc.w += xj * w.w;
    }
    *(float4*)&h[i * D + k0] = acc;
}

// ---------------- attention vectors: vr0=W0.T@ar0, vr1=W1.T@ar1, bvec=Wl2@bias -
__global__ __launch_bounds__(128) void attnvec_kernel(
    const float* __restrict__ Wg0, const float* __restrict__ ar0,
    const float* __restrict__ Wg1, const float* __restrict__ ar1,
    const float* __restrict__ Wl, const float* __restrict__ bias) {
    int k = threadIdx.x;
    float s0 = 0.f, s1 = 0.f, sb = 0.f;
    for (int j = 0; j < D; j++) {
        s0 += Wg0[j * D + k] * ar0[j];
        s1 += Wg1[j * D + k] * ar1[j];
        sb += Wl[k * (2 * D) + D + j] * bias[j];
    }
    g_vr0[k] = s0; g_vr1[k] = s1; g_bvec[k] = sb;
}

// ---------------- tensor-core GEMM (3xTF32): C = epi((A1[+A2]) @ W.T) ----------
// Tile: M=64 rows/block, N=128, K=128. 256 threads = 8 warps in 2(m) x 4(n) grid;
// each warp computes 32 rows x 32 cols via m16n8k8 mma (2 mt x 4 nt).
// smem = 64*132*4 + 128*132*4 = 101.4KB -> 2 CTAs/SM (16 warps resident).
#define SM_STRIDE 132
#define SMEM_TC ((64 + 128) * SM_STRIDE * 4)

__device__ __forceinline__ unsigned f2tf(float x) {
    unsigned r;
    asm("cvt.rna.tf32.f32 %0, %1;" : "=r"(r) : "f"(x));
    return r;
}

#define MMA_TF32(acc, a0, a1, a2, a3, b0, b1)                                   \
    asm volatile(                                                               \
        "mma.sync.aligned.m16n8k8.row.col.f32.tf32.tf32.f32 "                   \
        "{%0,%1,%2,%3},{%4,%5,%6,%7},{%8,%9},{%0,%1,%2,%3};"                    \
        : "+f"(acc[0]), "+f"(acc[1]), "+f"(acc[2]), "+f"(acc[3])                \
        : "r"(a0), "r"(a1), "r"(a2), "r"(a3), "r"(b0), "r"(b1))

__global__ __launch_bounds__(256, 2) void gemm_tc(
    const float* __restrict__ A1, const float* __restrict__ A2,
    const float* __restrict__ W, int ws,
    const float* __restrict__ addC, const float* __restrict__ addV,
    float* __restrict__ C, int doRelu, int nrows)
{
    extern __shared__ float sm[];
    float* As = sm;                       // [64][SM_STRIDE]
    float* Bs = sm + 64 * SM_STRIDE;      // [128][SM_STRIDE] (rows = output col n)
    int tid = threadIdx.x;
    int row0 = blockIdx.x * 64;

    // stage W tile (rows n, K contiguous)
    for (int i = tid; i < 128 * 32; i += 256) {
        int r = i >> 5, c4 = (i & 31) * 4;
        float4 v = *(const float4*)&W[(size_t)r * ws + c4];
        *(float4*)&Bs[r * SM_STRIDE + c4] = v;
    }
    // stage A tile (fp32, with optional A2 add)
    for (int i = tid; i < 64 * 32; i += 256) {
        int r = i >> 5, c4 = (i & 31) * 4;
        int gr = row0 + r;
        float4 v = make_float4(0.f, 0.f, 0.f, 0.f);
        if (gr < nrows) {
            v = *(const float4*)&A1[(size_t)gr * D + c4];
            if (A2) {
                float4 b = *(const float4*)&A2[(size_t)gr * D + c4];
                v.x += b.x; v.y += b.y; v.z += b.z; v.w += b.w;
            }
        }
        *(float4*)&As[r * SM_STRIDE + c4] = v;
    }
    __syncthreads();

    int lane = tid & 31, wid = tid >> 5;
    int wm = wid & 1, wn = wid >> 1;          // 2 x 4 warp grid
    int qr = lane >> 2, qc = lane & 3;

    float acc[2][4][4];
#pragma unroll
    for (int mt = 0; mt < 2; mt++)
#pragma unroll
        for (int nt = 0; nt < 4; nt++)
#pragma unroll
            for (int j = 0; j < 4; j++) acc[mt][nt][j] = 0.f;

    for (int k0 = 0; k0 < 128; k0 += 8) {
        unsigned ahi[2][4], alo[2][4];
#pragma unroll
        for (int mt = 0; mt < 2; mt++) {
            int rb = wm * 32 + mt * 16 + qr;
            float x0 = As[rb * SM_STRIDE + k0 + qc];
            float x1 = As[(rb + 8) * SM_STRIDE + k0 + qc];
            float x2 = As[rb * SM_STRIDE + k0 + qc + 4];
            float x3 = As[(rb + 8) * SM_STRIDE + k0 + qc + 4];
            ahi[mt][0] = f2tf(x0); alo[mt][0] = __float_as_uint(x0 - __uint_as_float(ahi[mt][0]));
            ahi[mt][1] = f2tf(x1); alo[mt][1] = __float_as_uint(x1 - __uint_as_float(ahi[mt][1]));
            ahi[mt][2] = f2tf(x2); alo[mt][2] = __float_as_uint(x2 - __uint_as_float(ahi[mt][2]));
            ahi[mt][3] = f2tf(x3); alo[mt][3] = __float_as_uint(x3 - __uint_as_float(ahi[mt][3]));
        }
#pragma unroll
        for (int nt = 0; nt < 4; nt++) {
            int cb = wn * 32 + nt * 8 + qr;
            float y0 = Bs[cb * SM_STRIDE + k0 + qc];
            float y1 = Bs[cb * SM_STRIDE + k0 + qc + 4];
            unsigned bhi0 = f2tf(y0), bhi1 = f2tf(y1);
            unsigned blo0 = __float_as_uint(y0 - __uint_as_float(bhi0));
            unsigned blo1 = __float_as_uint(y1 - __uint_as_float(bhi1));
#pragma unroll
            for (int mt = 0; mt < 2; mt++) {
                MMA_TF32(acc[mt][nt], alo[mt][0], alo[mt][1], alo[mt][2], alo[mt][3], bhi0, bhi1);
                MMA_TF32(acc[mt][nt], ahi[mt][0], ahi[mt][1], ahi[mt][2], ahi[mt][3], blo0, blo1);
                MMA_TF32(acc[mt][nt], ahi[mt][0], ahi[mt][1], ahi[mt][2], ahi[mt][3], bhi0, bhi1);
            }
        }
    }

    // epilogue
#pragma unroll
    for (int mt = 0; mt < 2; mt++) {
#pragma unroll
        for (int half = 0; half < 2; half++) {
            int gr = row0 + wm * 32 + mt * 16 + qr + half * 8;
            if (gr >= nrows) continue;
#pragma unroll
            for (int nt = 0; nt < 4; nt++) {
                int col = wn * 32 + nt * 8 + qc * 2;
                float v0 = acc[mt][nt][half * 2 + 0];
                float v1 = acc[mt][nt][half * 2 + 1];
                if (addC) {
                    float2 c = *(const float2*)&addC[(size_t)gr * D + col];
                    v0 += c.x; v1 += c.y;
                }
                if (addV) {
                    float2 b = *(const float2*)&addV[col];
                    v0 += b.x; v1 += b.y;
                }
                if (doRelu) { v0 = fmaxf(v0, 0.f); v1 = fmaxf(v1, 0.f); }
                float2 o = make_float2(v0, v1);
                *(float2*)&C[(size_t)gr * D + col] = o;
            }
        }
    }
}

// ---------------- attention logits (el/er) per node -----------------------------
__global__ __launch_bounds__(256) void scores_net(
    const float* __restrict__ al1, const float* __restrict__ al2,
    const float* __restrict__ ar2) {
    int warp = threadIdx.x >> 5, lane = threadIdx.x & 31;
    int i = blockIdx.x * 8 + warp;
    if (i >= N_NODES) return;
    int o = i * D + lane * 4, c = lane * 4;
    float4 hn = *(const float4*)&g_hnet[o];
    float4 h1 = *(const float4*)&g_hs1[o];
    float4 h2 = *(const float4*)&g_hs2[o];
    float4 v0 = *(const float4*)&g_vr0[c];
    float4 a1 = *(const float4*)&al1[c];
    float4 a2 = *(const float4*)&al2[c];
    float4 r2 = *(const float4*)&ar2[c];
    float d0 = hn.x * v0.x + hn.y * v0.y + hn.z * v0.z + hn.w * v0.w;
    float d1 = h1.x * a1.x + h1.y * a1.y + h1.z * a1.z + h1.w * a1.w;
    float d2 = h2.x * a2.x + h2.y * a2.y + h2.z * a2.z + h2.w * a2.w;
    float d3 = h2.x * r2.x + h2.y * r2.y + h2.z * r2.z + h2.w * r2.w;
#pragma unroll
    for (int off = 16; off; off >>= 1) {
        d0 += __shfl_xor_sync(0xffffffffu, d0, off);
        d1 += __shfl_xor_sync(0xffffffffu, d1, off);
        d2 += __shfl_xor_sync(0xffffffffu, d2, off);
        d3 += __shfl_xor_sync(0xffffffffu, d3, off);
    }
    if (lane == 0) {
        g_er[0][i] = d0;   // er for rel0 (dst=net)
        g_el[1][i] = d1;   // el for rel1 (src=net)
        g_el[2][i] = d2;   // el for rel2
        g_er[2][i] = d3;   // er for rel2 (dst=net, same W)
    }
}

__global__ __launch_bounds__(256) void scores_cell(const float* __restrict__ al0) {
    int warp = threadIdx.x >> 5, lane = threadIdx.x & 31;
    int i = blockIdx.x * 8 + warp;
    if (i >= N_NODES) return;
    int o = i * D + lane * 4, c = lane * 4;
    float4 h0 = *(const float4*)&g_hs0[o];
    float4 hc = *(const float4*)&g_hcell[o];
    float4 a0 = *(const float4*)&al0[c];
    float4 v1 = *(const float4*)&g_vr1[c];
    float d0 = h0.x * a0.x + h0.y * a0.y + h0.z * a0.z + h0.w * a0.w;
    float d1 = hc.x * v1.x + hc.y * v1.y + hc.z * v1.z + hc.w * v1.w;
#pragma unroll
    for (int off = 16; off; off >>= 1) {
        d0 += __shfl_xor_sync(0xffffffffu, d0, off);
        d1 += __shfl_xor_sync(0xffffffffu, d1, off);
    }
    if (lane == 0) {
        g_el[0][i] = d0;   // el for rel0 (src=cell)
        g_er[1][i] = d1;   // er for rel1 (dst=cell)
    }
}

// ---------------- CSR build ------------------------------------------------------
__global__ __launch_bounds__(256) void count3_kernel(
    const int* __restrict__ dst0, const int* __restrict__ dst1,
    const int* __restrict__ dst2) {
    int e = blockIdx.x * blockDim.x + threadIdx.x;
    if (e >= N_EDGES) return;
    atomicAdd(&g_cnt[0][dst0[e]], 1);
    atomicAdd(&g_cnt[1][dst1[e]], 1);
    atomicAdd(&g_cnt[2][dst2[e]], 1);
}

__global__ __launch_bounds__(256) void scan_kernel() {
    int r = blockIdx.x;
    const int* cnt = g_cnt[r];
    int* rp = g_rowptr[r];
    __shared__ int part[256];
    int t = threadIdx.x;
    const int CH = 391;  // 256*391 >= 100000
    int base = t * CH;
    int s = 0;
    for (int j = 0; j < CH; j++) {
        int idx = base + j;
        if (idx < N_NODES) s += cnt[idx];
    }
    part[t] = s;
    __syncthreads();
    if (t == 0) {
        int acc = 0;
        for (int i = 0; i < 256; i++) { int v = part[i]; part[i] = acc; acc += v; }
        rp[N_NODES] = acc;
    }
    __syncthreads();
    int acc = part[t];
    for (int j = 0; j < CH; j++) {
        int idx = base + j;
        if (idx < N_NODES) { rp[idx] = acc; acc += cnt[idx]; }
    }
}

__global__ __launch_bounds__(256) void fill_kernel(
    const int* __restrict__ src, const int* __restrict__ dst, int rel) {
    int e = blockIdx.x * blockDim.x + threadIdx.x;
    if (e >= N_EDGES) return;
    int s = src[e], d = dst[e];
    float x = g_el[rel][s] + g_er[rel][d];
    x = x > 0.f ? x : 0.2f * x;           // leaky_relu
    float w = __expf(x);                  // no max-subtraction needed (|x| small)
    int pos = atomicAdd(&g_cursor[rel][d], 1);
    int idx = g_rowptr[rel][d] + pos;
    g_csrc[rel][idx] = s;
    g_cw[rel][idx] = w;
}

// ---------------- atomic-free aggregation: agg[d] = sum(w*hs[src]) / sum(w) -----
__global__ __launch_bounds__(256) void aggregate_kernel(
    const float* __restrict__ hs, float* __restrict__ agg, int rel) {
    int warp = threadIdx.x >> 5, lane = threadIdx.x & 31;
    int i = blockIdx.x * 8 + warp;
    if (i >= N_NODES) return;
    int start = g_rowptr[rel][i];
    int end = g_rowptr[rel][i + 1];
    const float4* hv = (const float4*)hs;
    float4 acc = make_float4(0.f, 0.f, 0.f, 0.f);
    float wsum = 0.f;
    for (int t = start; t < end; t++) {
        int s = g_csrc[rel][t];
        float w = g_cw[rel][t];
        float4 v = hv[(size_t)s * 32 + lane];
        acc.x += w * v.x; acc.y += w * v.y; acc.z += w * v.z; acc.w += w * v.w;
        wsum += w;
    }
    float4 o = make_float4(0.f, 0.f, 0.f, 0.f);
    if (end > start) {
        float inv = 1.f / wsum;
        o = make_float4(acc.x * inv, acc.y * inv, acc.z * inv, acc.w * inv);
    }
    ((float4*)agg)[(size_t)i * 32 + lane] = o;
}

// ---------------- cell step0: out = relu(base_cell + bvec) ----------------------
__global__ __launch_bounds__(256) void cstep0_kernel(float* __restrict__ out) {
    int idx = blockIdx.x * blockDim.x + threadIdx.x;   // over ND/4 float4s
    if (idx >= ND / 4) return;
    float4 b = ((const float4*)g_bcell)[idx];
    int k = (idx & 31) * 4;
    float4 v = *(const float4*)&g_bvec[k];
    float4 r;
    r.x = fmaxf(b.x + v.x, 0.f); r.y = fmaxf(b.y + v.y, 0.f);
    r.z = fmaxf(b.z + v.z, 0.f); r.w = fmaxf(b.w + v.w, 0.f);
    ((float4*)out)[idx] = r;
}

// ---------------- host orchestration (3-stream fork/join DAG) -------------------
extern "C" void kernel_launch(void* const* d_in, const int* in_sizes, int n_in,
                              void* d_out, int out_size) {
    const float* x_net   = (const float*)d_in[0];
    const float* x_cell  = (const float*)d_in[1];
    const float* Wp_net  = (const float*)d_in[2];
    const float* Wp_cell = (const float*)d_in[3];
    const float* Wg0 = (const float*)d_in[4];
    const float* al0 = (const float*)d_in[5];
    const float* ar0 = (const float*)d_in[6];
    const float* Wg1 = (const float*)d_in[7];
    const float* al1 = (const float*)d_in[8];
    const float* ar1 = (const float*)d_in[9];
    const float* Wg2 = (const float*)d_in[10];
    const float* al2 = (const float*)d_in[11];
    const float* ar2 = (const float*)d_in[12];
    const float* Wl   = (const float*)d_in[13];
    const float* bias = (const float*)d_in[14];
    const int* src0 = (const int*)d_in[15];
    const int* dst0 = (const int*)d_in[16];
    const int* src1 = (const int*)d_in[17];
    const int* dst1 = (const int*)d_in[18];
    const int* src2 = (const int*)d_in[19];
    const int* dst2 = (const int*)d_in[20];
    float* out = (float*)d_out;

    float *hnet, *hcell, *hs0, *hs1, *hs2, *bnet, *bcell;
    float *agg0, *agg1, *agg2, *tmpA, *tmpB, *tmpC, *tmpD, *bvec;
    int *cnt, *cursor;
    cudaGetSymbolAddress((void**)&hnet,  g_hnet);
    cudaGetSymbolAddress((void**)&hcell, g_hcell);
    cudaGetSymbolAddress((void**)&hs0,   g_hs0);
    cudaGetSymbolAddress((void**)&hs1,   g_hs1);
    cudaGetSymbolAddress((void**)&hs2,   g_hs2);
    cudaGetSymbolAddress((void**)&bnet,  g_bnet);
    cudaGetSymbolAddress((void**)&bcell, g_bcell);
    cudaGetSymbolAddress((void**)&agg0,  g_agg0);
    cudaGetSymbolAddress((void**)&agg1,  g_agg1);
    cudaGetSymbolAddress((void**)&agg2,  g_agg2);
    cudaGetSymbolAddress((void**)&tmpA,  g_tmpA);
    cudaGetSymbolAddress((void**)&tmpB,  g_tmpB);
    cudaGetSymbolAddress((void**)&tmpC,  g_tmpC);
    cudaGetSymbolAddress((void**)&tmpD,  g_tmpD);
    cudaGetSymbolAddress((void**)&bvec,  g_bvec);
    cudaGetSymbolAddress((void**)&cnt,   g_cnt);
    cudaGetSymbolAddress((void**)&cursor, g_cursor);

    static cudaStream_t sA = 0, sB = 0, sC = 0;
    static cudaEvent_t evFork, eA1, eB1, eC1, eC2, eA3, eB3;
    static int init_done = 0;
    if (!init_done) {
        cudaFuncSetAttribute(gemm_tc, cudaFuncAttributeMaxDynamicSharedMemorySize, SMEM_TC);
        cudaStreamCreateWithFlags(&sA, cudaStreamNonBlocking);
        cudaStreamCreateWithFlags(&sB, cudaStreamNonBlocking);
        cudaStreamCreateWithFlags(&sC, cudaStreamNonBlocking);
        cudaEventCreateWithFlags(&evFork, cudaEventDisableTiming);
        cudaEventCreateWithFlags(&eA1, cudaEventDisableTiming);
        cudaEventCreateWithFlags(&eB1, cudaEventDisableTiming);
        cudaEventCreateWithFlags(&eC1, cudaEventDisableTiming);
        cudaEventCreateWithFlags(&eC2, cudaEventDisableTiming);
        cudaEventCreateWithFlags(&eA3, cudaEventDisableTiming);
        cudaEventCreateWithFlags(&eB3, cudaEventDisableTiming);
        init_done = 1;
    }

    const int GN = (N_NODES + 7) / 8;        // warp-per-node kernels
    const int GT = (N_NODES + 63) / 64;      // tensor gemm tiles (BM=64)
    const int GE = (N_EDGES + 255) / 256;
    const float* Wl2 = Wl + D;               // Wl[:, 128:], row stride 2*D

    // ---- pre-fork (origin stream): tiny attention-vector GEMVs ----
    attnvec_kernel<<<1, D, 0, 0>>>(Wg0, ar0, Wg1, ar1, Wl, bias);
    cudaEventRecord(evFork, 0);
    cudaStreamWaitEvent(sA, evFork, 0);
    cudaStreamWaitEvent(sB, evFork, 0);
    cudaStreamWaitEvent(sC, evFork, 0);

    // ---- branch C: CSR skeleton (independent of features) ----
    cudaMemsetAsync(cnt,    0, sizeof(int) * 3 * N_NODES, sC);
    cudaMemsetAsync(cursor, 0, sizeof(int) * 3 * N_NODES, sC);
    count3_kernel<<<GE, 256, 0, sC>>>(dst0, dst1, dst2);
    scan_kernel<<<3, 256, 0, sC>>>();
    cudaEventRecord(eC1, sC);

    // ---- branch A: net-side features ----
    proj_kernel<<<GN, 256, 0, sA>>>(x_net, Wp_net, hnet);
    gemm_tc<<<GT, 256, SMEM_TC, sA>>>(hnet, nullptr, Wg1, D,     nullptr, nullptr, hs1,  0, N_NODES);
    gemm_tc<<<GT, 256, SMEM_TC, sA>>>(hnet, nullptr, Wg2, D,     nullptr, nullptr, hs2,  0, N_NODES);
    gemm_tc<<<GT, 256, SMEM_TC, sA>>>(hnet, nullptr, Wl,  2 * D, nullptr, nullptr, bnet, 0, N_NODES);
    scores_net<<<GN, 256, 0, sA>>>(al1, al2, ar2);
    cudaEventRecord(eA1, sA);

    // ---- branch B: cell-side features ----
    proj_kernel<<<GN, 256, 0, sB>>>(x_cell, Wp_cell, hcell);
    gemm_tc<<<GT, 256, SMEM_TC, sB>>>(hcell, nullptr, Wg0, D,     nullptr, nullptr, hs0,  0, N_NODES);
    gemm_tc<<<GT, 256, SMEM_TC, sB>>>(hcell, nullptr, Wl,  2 * D, nullptr, nullptr, bcell, 0, N_NODES);
    scores_cell<<<GN, 256, 0, sB>>>(al0);
    cudaEventRecord(eB1, sB);

    // ---- join J1: scores + CSR skeleton complete everywhere ----
    cudaStreamWaitEvent(sA, eB1, 0); cudaStreamWaitEvent(sA, eC1, 0);
    cudaStreamWaitEvent(sB, eA1, 0); cudaStreamWaitEvent(sB, eC1, 0);
    cudaStreamWaitEvent(sC, eA1, 0); cudaStreamWaitEvent(sC, eB1, 0);

    // ---- per-relation fill + aggregate, one relation per stream ----
    fill_kernel<<<GE, 256, 0, sA>>>(src0, dst0, 0);
    aggregate_kernel<<<GN, 256, 0, sA>>>(hs0, agg0, 0);
    fill_kernel<<<GE, 256, 0, sB>>>(src1, dst1, 1);
    aggregate_kernel<<<GN, 256, 0, sB>>>(hs1, agg1, 1);
    fill_kernel<<<GE, 256, 0, sC>>>(src2, dst2, 2);
    aggregate_kernel<<<GN, 256, 0, sC>>>(hs2, agg2, 2);
    cudaEventRecord(eC2, sC);

    // ---- branch A: net output chain (needs agg0 local, agg2 from C) ----
    gemm_tc<<<GT, 256, SMEM_TC, sA>>>(agg0, nullptr, Wl2, 2 * D, bnet, bvec, tmpA, 1, N_NODES);
    gemm_tc<<<GT, 256, SMEM_TC, sA>>>(tmpA, nullptr, Wl2, 2 * D, bnet, bvec, tmpB, 1, N_NODES);
    cudaStreamWaitEvent(sA, eC2, 0);
    gemm_tc<<<GT, 256, SMEM_TC, sA>>>(tmpB, agg2,    Wl2, 2 * D, bnet, bvec, out,  1, N_NODES);
    cudaEventRecord(eA3, sA);

    // ---- branch B: cell output chain (agg1 local) ----
    cstep0_kernel<<<(ND / 4 + 255) / 256, 256, 0, sB>>>(tmpC);
    gemm_tc<<<GT, 256, SMEM_TC, sB>>>(tmpC, agg1,    Wl2, 2 * D, bcell, bvec, tmpD, 1, N_NODES);
    gemm_tc<<<GT, 256, SMEM_TC, sB>>>(tmpD, nullptr, Wl2, 2 * D, bcell, bvec, out + ND, 1, N_NODES);
    cudaEventRecord(eB3, sB);

    // ---- join back to origin stream ----
    cudaStreamWaitEvent(0, eA3, 0);
    cudaStreamWaitEvent(0, eB3, 0);
}

// round 10
// speedup vs baseline: 1.6057x; 1.0754x over previous
#include <cuda_runtime.h>

#define N_NODES 100000
#define N_EDGES 600000
#define D 128
#define DIN 16
#define ND (N_NODES * D)

// ---------------- scratch (static __device__ arrays; no allocs) ----------------
__device__ float g_hnet[ND], g_hcell[ND];                 // projected features
__device__ float g_hs0[ND], g_hs1[ND], g_hs2[ND];         // h_src per relation
__device__ float g_bnet[ND], g_bcell[ND];                 // feat @ Wl1.T
__device__ float g_agg0[ND], g_agg1[ND], g_agg2[ND];      // normalized GAT outputs
__device__ float g_tmpA[ND], g_tmpB[ND];                  // net chain intermediates
__device__ float g_tmpC[ND], g_tmpD[ND];                  // cell chain intermediates
__device__ float g_el[3][N_NODES], g_er[3][N_NODES];
__device__ float g_vr0[D], g_vr1[D], g_bvec[D];
__device__ int   g_cnt[3][N_NODES];
__device__ int   g_rowptr[3][N_NODES + 1];
__device__ int   g_cursor[3][N_NODES];
__device__ int   g_csrc[3][N_EDGES];
__device__ float g_cw[3][N_EDGES];

// ---------------- feature projection: h = x @ Wp.T  ([N,16] -> [N,128]) --------
// v3: W float4s hoisted into registers once per warp, amortized over 4 nodes.
__global__ __launch_bounds__(256) void proj_kernel(
    const float* __restrict__ x, const float* __restrict__ Wp,
    float* __restrict__ h) {
    __shared__ float Wt[DIN][D];          // Wt[j][k] = Wp[k][j]
    int tid = threadIdx.x;
    for (int i = tid; i < D * DIN; i += 256) {
        int k = i >> 4, j = i & 15;       // Wp row k, col j
        Wt[j][k] = Wp[i];
    }
    __syncthreads();
    int warp = tid >> 5, lane = tid & 31;
    int k0 = lane * 4;
    float4 w[16];
#pragma unroll
    for (int j = 0; j < 16; j++) w[j] = *(const float4*)&Wt[j][k0];

    int base = blockIdx.x * 32 + warp * 4;   // 4 nodes per warp
#pragma unroll
    for (int nn = 0; nn < 4; nn++) {
        int i = base + nn;
        if (i >= N_NODES) return;
        float xv = x[i * DIN + (lane & 15)];
        float4 acc = make_float4(0.f, 0.f, 0.f, 0.f);
#pragma unroll
        for (int j = 0; j < 16; j++) {
            float xj = __shfl_sync(0xffffffffu, xv, j);
            acc.x += xj * w[j].x; acc.y += xj * w[j].y;
            acc.z += xj * w[j].z; acc.w += xj * w[j].w;
        }
        *(float4*)&h[i * D + k0] = acc;
    }
}

// ---------------- attention vectors: vr0=W0.T@ar0, vr1=W1.T@ar1, bvec=Wl2@bias -
__global__ __launch_bounds__(128) void attnvec_kernel(
    const float* __restrict__ Wg0, const float* __restrict__ ar0,
    const float* __restrict__ Wg1, const float* __restrict__ ar1,
    const float* __restrict__ Wl, const float* __restrict__ bias) {
    int k = threadIdx.x;
    float s0 = 0.f, s1 = 0.f, sb = 0.f;
    for (int j = 0; j < D; j++) {
        s0 += Wg0[j * D + k] * ar0[j];
        s1 += Wg1[j * D + k] * ar1[j];
        sb += Wl[k * (2 * D) + D + j] * bias[j];
    }
    g_vr0[k] = s0; g_vr1[k] = s1; g_bvec[k] = sb;
}

// ---------------- 3xTF32 mma building blocks ------------------------------------
#define SM_STRIDE 132
#define SMEM_TC ((64 + 128) * SM_STRIDE * 4)

__device__ __forceinline__ unsigned f2tf(float x) {
    unsigned r;
    asm("cvt.rna.tf32.f32 %0, %1;" : "=r"(r) : "f"(x));
    return r;
}

#define MMA_TF32(acc, a0, a1, a2, a3, b0, b1)                                   \
    asm volatile(                                                               \
        "mma.sync.aligned.m16n8k8.row.col.f32.tf32.tf32.f32 "                   \
        "{%0,%1,%2,%3},{%4,%5,%6,%7},{%8,%9},{%0,%1,%2,%3};"                    \
        : "+f"(acc[0]), "+f"(acc[1]), "+f"(acc[2]), "+f"(acc[3])                \
        : "r"(a0), "r"(a1), "r"(a2), "r"(a3), "r"(b0), "r"(b1))

// Core mma loop over the staged As/Bs tiles. Each warp: 32 rows x 32 cols.
__device__ __forceinline__ void mma_tile_compute(
    const float* As, const float* Bs, float acc[2][4][4],
    int wm, int wn, int qr, int qc)
{
#pragma unroll
    for (int mt = 0; mt < 2; mt++)
#pragma unroll
        for (int nt = 0; nt < 4; nt++)
#pragma unroll
            for (int j = 0; j < 4; j++) acc[mt][nt][j] = 0.f;

    for (int k0 = 0; k0 < 128; k0 += 8) {
        unsigned ahi[2][4], alo[2][4];
#pragma unroll
        for (int mt = 0; mt < 2; mt++) {
            int rb = wm * 32 + mt * 16 + qr;
            float x0 = As[rb * SM_STRIDE + k0 + qc];
            float x1 = As[(rb + 8) * SM_STRIDE + k0 + qc];
            float x2 = As[rb * SM_STRIDE + k0 + qc + 4];
            float x3 = As[(rb + 8) * SM_STRIDE + k0 + qc + 4];
            ahi[mt][0] = f2tf(x0); alo[mt][0] = __float_as_uint(x0 - __uint_as_float(ahi[mt][0]));
            ahi[mt][1] = f2tf(x1); alo[mt][1] = __float_as_uint(x1 - __uint_as_float(ahi[mt][1]));
            ahi[mt][2] = f2tf(x2); alo[mt][2] = __float_as_uint(x2 - __uint_as_float(ahi[mt][2]));
            ahi[mt][3] = f2tf(x3); alo[mt][3] = __float_as_uint(x3 - __uint_as_float(ahi[mt][3]));
        }
#pragma unroll
        for (int nt = 0; nt < 4; nt++) {
            int cb = wn * 32 + nt * 8 + qr;
            float y0 = Bs[cb * SM_STRIDE + k0 + qc];
            float y1 = Bs[cb * SM_STRIDE + k0 + qc + 4];
            unsigned bhi0 = f2tf(y0), bhi1 = f2tf(y1);
            unsigned blo0 = __float_as_uint(y0 - __uint_as_float(bhi0));
            unsigned blo1 = __float_as_uint(y1 - __uint_as_float(bhi1));
#pragma unroll
            for (int mt = 0; mt < 2; mt++) {
                MMA_TF32(acc[mt][nt], alo[mt][0], alo[mt][1], alo[mt][2], alo[mt][3], bhi0, bhi1);
                MMA_TF32(acc[mt][nt], ahi[mt][0], ahi[mt][1], ahi[mt][2], ahi[mt][3], blo0, blo1);
                MMA_TF32(acc[mt][nt], ahi[mt][0], ahi[mt][1], ahi[mt][2], ahi[mt][3], bhi0, bhi1);
            }
        }
    }
}

// ---------------- chain GEMM with epilogue: C = epi((A1[+A2]) @ W.T) ------------
__global__ __launch_bounds__(256, 2) void gemm_tc(
    const float* __restrict__ A1, const float* __restrict__ A2,
    const float* __restrict__ W, int ws,
    const float* __restrict__ addC, const float* __restrict__ addV,
    float* __restrict__ C, int doRelu, int nrows)
{
    extern __shared__ float sm[];
    float* As = sm;                       // [64][SM_STRIDE]
    float* Bs = sm + 64 * SM_STRIDE;      // [128][SM_STRIDE]
    int tid = threadIdx.x;
    int row0 = blockIdx.x * 64;

    for (int i = tid; i < 128 * 32; i += 256) {
        int r = i >> 5, c4 = (i & 31) * 4;
        float4 v = *(const float4*)&W[(size_t)r * ws + c4];
        *(float4*)&Bs[r * SM_STRIDE + c4] = v;
    }
    for (int i = tid; i < 64 * 32; i += 256) {
        int r = i >> 5, c4 = (i & 31) * 4;
        int gr = row0 + r;
        float4 v = make_float4(0.f, 0.f, 0.f, 0.f);
        if (gr < nrows) {
            v = *(const float4*)&A1[(size_t)gr * D + c4];
            if (A2) {
                float4 b = *(const float4*)&A2[(size_t)gr * D + c4];
                v.x += b.x; v.y += b.y; v.z += b.z; v.w += b.w;
            }
        }
        *(float4*)&As[r * SM_STRIDE + c4] = v;
    }
    __syncthreads();

    int lane = tid & 31, wid = tid >> 5;
    int wm = wid & 1, wn = wid >> 1;
    int qr = lane >> 2, qc = lane & 3;

    float acc[2][4][4];
    mma_tile_compute(As, Bs, acc, wm, wn, qr, qc);

#pragma unroll
    for (int mt = 0; mt < 2; mt++) {
#pragma unroll
        for (int half = 0; half < 2; half++) {
            int gr = row0 + wm * 32 + mt * 16 + qr + half * 8;
            if (gr >= nrows) continue;
#pragma unroll
            for (int nt = 0; nt < 4; nt++) {
                int col = wn * 32 + nt * 8 + qc * 2;
                float v0 = acc[mt][nt][half * 2 + 0];
                float v1 = acc[mt][nt][half * 2 + 1];
                if (addC) {
                    float2 c = *(const float2*)&addC[(size_t)gr * D + col];
                    v0 += c.x; v1 += c.y;
                }
                if (addV) {
                    float2 b = *(const float2*)&addV[col];
                    v0 += b.x; v1 += b.y;
                }
                if (doRelu) { v0 = fmaxf(v0, 0.f); v1 = fmaxf(v1, 0.f); }
                float2 o = make_float2(v0, v1);
                *(float2*)&C[(size_t)gr * D + col] = o;
            }
        }
    }
}

// ---------------- fused multi-weight GEMM: A staged once, up to 3 weights -------
__global__ __launch_bounds__(256, 2) void gemm_multi(
    const float* __restrict__ A,
    const float* __restrict__ W0, int ws0, float* __restrict__ C0,
    const float* __restrict__ W1, int ws1, float* __restrict__ C1,
    const float* __restrict__ W2, int ws2, float* __restrict__ C2,
    int nrows)
{
    extern __shared__ float sm[];
    float* As = sm;
    float* Bs = sm + 64 * SM_STRIDE;
    int tid = threadIdx.x;
    int row0 = blockIdx.x * 64;

    const float* Wlist[3] = {W0, W1, W2};
    int wslist[3] = {ws0, ws1, ws2};
    float* Clist[3] = {C0, C1, C2};

    // stage A tile once
    for (int i = tid; i < 64 * 32; i += 256) {
        int r = i >> 5, c4 = (i & 31) * 4;
        int gr = row0 + r;
        float4 v = make_float4(0.f, 0.f, 0.f, 0.f);
        if (gr < nrows) v = *(const float4*)&A[(size_t)gr * D + c4];
        *(float4*)&As[r * SM_STRIDE + c4] = v;
    }
    // stage first W
    {
        const float* W = Wlist[0];
        int ws = wslist[0];
        for (int i = tid; i < 128 * 32; i += 256) {
            int r = i >> 5, c4 = (i & 31) * 4;
            float4 v = *(const float4*)&W[(size_t)r * ws + c4];
            *(float4*)&Bs[r * SM_STRIDE + c4] = v;
        }
    }
    __syncthreads();

    int lane = tid & 31, wid = tid >> 5;
    int wm = wid & 1, wn = wid >> 1;
    int qr = lane >> 2, qc = lane & 3;

#pragma unroll 1
    for (int s = 0; s < 3; s++) {
        if (!Wlist[s]) break;
        float acc[2][4][4];
        mma_tile_compute(As, Bs, acc, wm, wn, qr, qc);
        __syncthreads();   // all warps done reading Bs

        // stage next W (overlaps with epilogue stores below across warps)
        if (s + 1 < 3 && Wlist[s + 1]) {
            const float* W = Wlist[s + 1];
            int ws = wslist[s + 1];
            for (int i = tid; i < 128 * 32; i += 256) {
                int r = i >> 5, c4 = (i & 31) * 4;
                float4 v = *(const float4*)&W[(size_t)r * ws + c4];
                *(float4*)&Bs[r * SM_STRIDE + c4] = v;
            }
        }

        // epilogue: plain store
        float* C = Clist[s];
#pragma unroll
        for (int mt = 0; mt < 2; mt++) {
#pragma unroll
            for (int half = 0; half < 2; half++) {
                int gr = row0 + wm * 32 + mt * 16 + qr + half * 8;
                if (gr >= nrows) continue;
#pragma unroll
                for (int nt = 0; nt < 4; nt++) {
                    int col = wn * 32 + nt * 8 + qc * 2;
                    float2 o = make_float2(acc[mt][nt][half * 2 + 0],
                                           acc[mt][nt][half * 2 + 1]);
                    *(float2*)&C[(size_t)gr * D + col] = o;
                }
            }
        }
        __syncthreads();   // next Bs fully staged before next compute
    }
}

// ---------------- attention logits (el/er) per node -----------------------------
__global__ __launch_bounds__(256) void scores_net(
    const float* __restrict__ al1, const float* __restrict__ al2,
    const float* __restrict__ ar2) {
    int warp = threadIdx.x >> 5, lane = threadIdx.x & 31;
    int i = blockIdx.x * 8 + warp;
    if (i >= N_NODES) return;
    int o = i * D + lane * 4, c = lane * 4;
    float4 hn = *(const float4*)&g_hnet[o];
    float4 h1 = *(const float4*)&g_hs1[o];
    float4 h2 = *(const float4*)&g_hs2[o];
    float4 v0 = *(const float4*)&g_vr0[c];
    float4 a1 = *(const float4*)&al1[c];
    float4 a2 = *(const float4*)&al2[c];
    float4 r2 = *(const float4*)&ar2[c];
    float d0 = hn.x * v0.x + hn.y * v0.y + hn.z * v0.z + hn.w * v0.w;
    float d1 = h1.x * a1.x + h1.y * a1.y + h1.z * a1.z + h1.w * a1.w;
    float d2 = h2.x * a2.x + h2.y * a2.y + h2.z * a2.z + h2.w * a2.w;
    float d3 = h2.x * r2.x + h2.y * r2.y + h2.z * r2.z + h2.w * r2.w;
#pragma unroll
    for (int off = 16; off; off >>= 1) {
        d0 += __shfl_xor_sync(0xffffffffu, d0, off);
        d1 += __shfl_xor_sync(0xffffffffu, d1, off);
        d2 += __shfl_xor_sync(0xffffffffu, d2, off);
        d3 += __shfl_xor_sync(0xffffffffu, d3, off);
    }
    if (lane == 0) {
        g_er[0][i] = d0;   // er for rel0 (dst=net)
        g_el[1][i] = d1;   // el for rel1 (src=net)
        g_el[2][i] = d2;   // el for rel2
        g_er[2][i] = d3;   // er for rel2 (dst=net, same W)
    }
}

__global__ __launch_bounds__(256) void scores_cell(const float* __restrict__ al0) {
    int warp = threadIdx.x >> 5, lane = threadIdx.x & 31;
    int i = blockIdx.x * 8 + warp;
    if (i >= N_NODES) return;
    int o = i * D + lane * 4, c = lane * 4;
    float4 h0 = *(const float4*)&g_hs0[o];
    float4 hc = *(const float4*)&g_hcell[o];
    float4 a0 = *(const float4*)&al0[c];
    float4 v1 = *(const float4*)&g_vr1[c];
    float d0 = h0.x * a0.x + h0.y * a0.y + h0.z * a0.z + h0.w * a0.w;
    float d1 = hc.x * v1.x + hc.y * v1.y + hc.z * v1.z + hc.w * v1.w;
#pragma unroll
    for (int off = 16; off; off >>= 1) {
        d0 += __shfl_xor_sync(0xffffffffu, d0, off);
        d1 += __shfl_xor_sync(0xffffffffu, d1, off);
    }
    if (lane == 0) {
        g_el[0][i] = d0;   // el for rel0 (src=cell)
        g_er[1][i] = d1;   // er for rel1 (dst=cell)
    }
}

// ---------------- CSR build ------------------------------------------------------
__global__ __launch_bounds__(256) void count3_kernel(
    const int* __restrict__ dst0, const int* __restrict__ dst1,
    const int* __restrict__ dst2) {
    int e = blockIdx.x * blockDim.x + threadIdx.x;
    if (e >= N_EDGES) return;
    atomicAdd(&g_cnt[0][dst0[e]], 1);
    atomicAdd(&g_cnt[1][dst1[e]], 1);
    atomicAdd(&g_cnt[2][dst2[e]], 1);
}

__global__ __launch_bounds__(256) void scan_kernel() {
    int r = blockIdx.x;
    const int* cnt = g_cnt[r];
    int* rp = g_rowptr[r];
    __shared__ int part[256];
    int t = threadIdx.x;
    const int CH = 391;  // 256*391 >= 100000
    int base = t * CH;
    int s = 0;
    for (int j = 0; j < CH; j++) {
        int idx = base + j;
        if (idx < N_NODES) s += cnt[idx];
    }
    part[t] = s;
    __syncthreads();
    if (t == 0) {
        int acc = 0;
        for (int i = 0; i < 256; i++) { int v = part[i]; part[i] = acc; acc += v; }
        rp[N_NODES] = acc;
    }
    __syncthreads();
    int acc = part[t];
    for (int j = 0; j < CH; j++) {
        int idx = base + j;
        if (idx < N_NODES) { rp[idx] = acc; acc += cnt[idx]; }
    }
}

__global__ __launch_bounds__(256) void fill_kernel(
    const int* __restrict__ src, const int* __restrict__ dst, int rel) {
    int e = blockIdx.x * blockDim.x + threadIdx.x;
    if (e >= N_EDGES) return;
    int s = src[e], d = dst[e];
    float x = g_el[rel][s] + g_er[rel][d];
    x = x > 0.f ? x : 0.2f * x;           // leaky_relu
    float w = __expf(x);                  // no max-subtraction needed (|x| small)
    int pos = atomicAdd(&g_cursor[rel][d], 1);
    int idx = g_rowptr[rel][d] + pos;
    g_csrc[rel][idx] = s;
    g_cw[rel][idx] = w;
}

// ---------------- atomic-free aggregation: agg[d] = sum(w*hs[src]) / sum(w) -----
__global__ __launch_bounds__(256) void aggregate_kernel(
    const float* __restrict__ hs, float* __restrict__ agg, int rel) {
    int warp = threadIdx.x >> 5, lane = threadIdx.x & 31;
    int i = blockIdx.x * 8 + warp;
    if (i >= N_NODES) return;
    int start = g_rowptr[rel][i];
    int end = g_rowptr[rel][i + 1];
    const float4* hv = (const float4*)hs;
    float4 acc = make_float4(0.f, 0.f, 0.f, 0.f);
    float wsum = 0.f;
    for (int t = start; t < end; t++) {
        int s = g_csrc[rel][t];
        float w = g_cw[rel][t];
        float4 v = hv[(size_t)s * 32 + lane];
        acc.x += w * v.x; acc.y += w * v.y; acc.z += w * v.z; acc.w += w * v.w;
        wsum += w;
    }
    float4 o = make_float4(0.f, 0.f, 0.f, 0.f);
    if (end > start) {
        float inv = 1.f / wsum;
        o = make_float4(acc.x * inv, acc.y * inv, acc.z * inv, acc.w * inv);
    }
    ((float4*)agg)[(size_t)i * 32 + lane] = o;
}

// ---------------- cell step0: out = relu(base_cell + bvec) ----------------------
__global__ __launch_bounds__(256) void cstep0_kernel(float* __restrict__ out) {
    int idx = blockIdx.x * blockDim.x + threadIdx.x;   // over ND/4 float4s
    if (idx >= ND / 4) return;
    float4 b = ((const float4*)g_bcell)[idx];
    int k = (idx & 31) * 4;
    float4 v = *(const float4*)&g_bvec[k];
    float4 r;
    r.x = fmaxf(b.x + v.x, 0.f); r.y = fmaxf(b.y + v.y, 0.f);
    r.z = fmaxf(b.z + v.z, 0.f); r.w = fmaxf(b.w + v.w, 0.f);
    ((float4*)out)[idx] = r;
}

// ---------------- host orchestration (3-stream fork/join DAG) -------------------
extern "C" void kernel_launch(void* const* d_in, const int* in_sizes, int n_in,
                              void* d_out, int out_size) {
    const float* x_net   = (const float*)d_in[0];
    const float* x_cell  = (const float*)d_in[1];
    const float* Wp_net  = (const float*)d_in[2];
    const float* Wp_cell = (const float*)d_in[3];
    const float* Wg0 = (const float*)d_in[4];
    const float* al0 = (const float*)d_in[5];
    const float* ar0 = (const float*)d_in[6];
    const float* Wg1 = (const float*)d_in[7];
    const float* al1 = (const float*)d_in[8];
    const float* ar1 = (const float*)d_in[9];
    const float* Wg2 = (const float*)d_in[10];
    const float* al2 = (const float*)d_in[11];
    const float* ar2 = (const float*)d_in[12];
    const float* Wl   = (const float*)d_in[13];
    const float* bias = (const float*)d_in[14];
    const int* src0 = (const int*)d_in[15];
    const int* dst0 = (const int*)d_in[16];
    const int* src1 = (const int*)d_in[17];
    const int* dst1 = (const int*)d_in[18];
    const int* src2 = (const int*)d_in[19];
    const int* dst2 = (const int*)d_in[20];
    float* out = (float*)d_out;

    float *hnet, *hcell, *hs0, *hs1, *hs2, *bnet, *bcell;
    float *agg0, *agg1, *agg2, *tmpA, *tmpB, *tmpC, *tmpD, *bvec;
    int *cnt, *cursor;
    cudaGetSymbolAddress((void**)&hnet,  g_hnet);
    cudaGetSymbolAddress((void**)&hcell, g_hcell);
    cudaGetSymbolAddress((void**)&hs0,   g_hs0);
    cudaGetSymbolAddress((void**)&hs1,   g_hs1);
    cudaGetSymbolAddress((void**)&hs2,   g_hs2);
    cudaGetSymbolAddress((void**)&bnet,  g_bnet);
    cudaGetSymbolAddress((void**)&bcell, g_bcell);
    cudaGetSymbolAddress((void**)&agg0,  g_agg0);
    cudaGetSymbolAddress((void**)&agg1,  g_agg1);
    cudaGetSymbolAddress((void**)&agg2,  g_agg2);
    cudaGetSymbolAddress((void**)&tmpA,  g_tmpA);
    cudaGetSymbolAddress((void**)&tmpB,  g_tmpB);
    cudaGetSymbolAddress((void**)&tmpC,  g_tmpC);
    cudaGetSymbolAddress((void**)&tmpD,  g_tmpD);
    cudaGetSymbolAddress((void**)&bvec,  g_bvec);
    cudaGetSymbolAddress((void**)&cnt,   g_cnt);
    cudaGetSymbolAddress((void**)&cursor, g_cursor);

    static cudaStream_t sA = 0, sB = 0, sC = 0;
    static cudaEvent_t evFork, eA1, eB1, eC1, eC2, eA3, eB3;
    static int init_done = 0;
    if (!init_done) {
        cudaFuncSetAttribute(gemm_tc,    cudaFuncAttributeMaxDynamicSharedMemorySize, SMEM_TC);
        cudaFuncSetAttribute(gemm_multi, cudaFuncAttributeMaxDynamicSharedMemorySize, SMEM_TC);
        cudaStreamCreateWithFlags(&sA, cudaStreamNonBlocking);
        cudaStreamCreateWithFlags(&sB, cudaStreamNonBlocking);
        cudaStreamCreateWithFlags(&sC, cudaStreamNonBlocking);
        cudaEventCreateWithFlags(&evFork, cudaEventDisableTiming);
        cudaEventCreateWithFlags(&eA1, cudaEventDisableTiming);
        cudaEventCreateWithFlags(&eB1, cudaEventDisableTiming);
        cudaEventCreateWithFlags(&eC1, cudaEventDisableTiming);
        cudaEventCreateWithFlags(&eC2, cudaEventDisableTiming);
        cudaEventCreateWithFlags(&eA3, cudaEventDisableTiming);
        cudaEventCreateWithFlags(&eB3, cudaEventDisableTiming);
        init_done = 1;
    }

    const int GN = (N_NODES + 7) / 8;        // warp-per-node kernels
    const int GP = (N_NODES + 31) / 32;      // proj: 4 nodes/warp, 8 warps
    const int GT = (N_NODES + 63) / 64;      // tensor gemm tiles (BM=64)
    const int GE = (N_EDGES + 255) / 256;
    const float* Wl2 = Wl + D;               // Wl[:, 128:], row stride 2*D

    // ---- pre-fork (origin stream): tiny attention-vector GEMVs ----
    attnvec_kernel<<<1, D, 0, 0>>>(Wg0, ar0, Wg1, ar1, Wl, bias);
    cudaEventRecord(evFork, 0);
    cudaStreamWaitEvent(sA, evFork, 0);
    cudaStreamWaitEvent(sB, evFork, 0);
    cudaStreamWaitEvent(sC, evFork, 0);

    // ---- branch C: CSR skeleton (independent of features) ----
    cudaMemsetAsync(cnt,    0, sizeof(int) * 3 * N_NODES, sC);
    cudaMemsetAsync(cursor, 0, sizeof(int) * 3 * N_NODES, sC);
    count3_kernel<<<GE, 256, 0, sC>>>(dst0, dst1, dst2);
    scan_kernel<<<3, 256, 0, sC>>>();
    cudaEventRecord(eC1, sC);

    // ---- branch A: net-side features (fused 3-weight GEMM) ----
    proj_kernel<<<GP, 256, 0, sA>>>(x_net, Wp_net, hnet);
    gemm_multi<<<GT, 256, SMEM_TC, sA>>>(hnet,
        Wg1, D, hs1, Wg2, D, hs2, Wl, 2 * D, bnet, N_NODES);
    scores_net<<<GN, 256, 0, sA>>>(al1, al2, ar2);
    cudaEventRecord(eA1, sA);

    // ---- branch B: cell-side features (fused 2-weight GEMM) ----
    proj_kernel<<<GP, 256, 0, sB>>>(x_cell, Wp_cell, hcell);
    gemm_multi<<<GT, 256, SMEM_TC, sB>>>(hcell,
        Wg0, D, hs0, Wl, 2 * D, bcell, nullptr, 0, nullptr, N_NODES);
    scores_cell<<<GN, 256, 0, sB>>>(al0);
    cudaEventRecord(eB1, sB);

    // ---- join J1: scores + CSR skeleton complete everywhere ----
    cudaStreamWaitEvent(sA, eB1, 0); cudaStreamWaitEvent(sA, eC1, 0);
    cudaStreamWaitEvent(sB, eA1, 0); cudaStreamWaitEvent(sB, eC1, 0);
    cudaStreamWaitEvent(sC, eA1, 0); cudaStreamWaitEvent(sC, eB1, 0);

    // ---- per-relation fill + aggregate, one relation per stream ----
    fill_kernel<<<GE, 256, 0, sA>>>(src0, dst0, 0);
    aggregate_kernel<<<GN, 256, 0, sA>>>(hs0, agg0, 0);
    fill_kernel<<<GE, 256, 0, sB>>>(src1, dst1, 1);
    aggregate_kernel<<<GN, 256, 0, sB>>>(hs1, agg1, 1);
    fill_kernel<<<GE, 256, 0, sC>>>(src2, dst2, 2);
    aggregate_kernel<<<GN, 256, 0, sC>>>(hs2, agg2, 2);
    cudaEventRecord(eC2, sC);

    // ---- branch A: net output chain (needs agg0 local, agg2 from C) ----
    gemm_tc<<<GT, 256, SMEM_TC, sA>>>(agg0, nullptr, Wl2, 2 * D, bnet, bvec, tmpA, 1, N_NODES);
    gemm_tc<<<GT, 256, SMEM_TC, sA>>>(tmpA, nullptr, Wl2, 2 * D, bnet, bvec, tmpB, 1, N_NODES);
    cudaStreamWaitEvent(sA, eC2, 0);
    gemm_tc<<<GT, 256, SMEM_TC, sA>>>(tmpB, agg2,    Wl2, 2 * D, bnet, bvec, out,  1, N_NODES);
    cudaEventRecord(eA3, sA);

    // ---- branch B: cell output chain (agg1 local) ----
    cstep0_kernel<<<(ND / 4 + 255) / 256, 256, 0, sB>>>(tmpC);
    gemm_tc<<<GT, 256, SMEM_TC, sB>>>(tmpC, agg1,    Wl2, 2 * D, bcell, bvec, tmpD, 1, N_NODES);
    gemm_tc<<<GT, 256, SMEM_TC, sB>>>(tmpD, nullptr, Wl2, 2 * D, bcell, bvec, out + ND, 1, N_NODES);
    cudaEventRecord(eB3, sB);

    // ---- join back to origin stream ----
    cudaStreamWaitEvent(0, eA3, 0);
    cudaStreamWaitEvent(0, eB3, 0);
}

// round 11
// speedup vs baseline: 1.7908x; 1.1152x over previous
#include <cuda_runtime.h>

#define N_NODES 100000
#define N_EDGES 600000
#define D 128
#define DIN 16
#define ND (N_NODES * D)

// ---------------- scratch (static __device__ arrays; no allocs) ----------------
__device__ float g_hnet[ND], g_hcell[ND];                 // projected features
__device__ float g_hs0[ND], g_hs1[ND], g_hs2[ND];         // h_src per relation
__device__ float g_bnet[ND], g_bcell[ND];                 // feat @ Wl1.T
__device__ float g_agg0[ND], g_agg1[ND], g_agg2[ND];      // normalized GAT outputs
__device__ float g_el[3][N_NODES], g_er[3][N_NODES];
__device__ float g_vr0[D], g_vr1[D], g_bvec[D];
__device__ int   g_cnt[3][N_NODES];
__device__ int   g_rowptr[3][N_NODES + 1];
__device__ int   g_cursor[3][N_NODES];
__device__ int   g_csrc[3][N_EDGES];
__device__ float g_cw[3][N_EDGES];

// ---------------- feature projection: h = x @ Wp.T  ([N,16] -> [N,128]) --------
__global__ __launch_bounds__(256) void proj_kernel(
    const float* __restrict__ x, const float* __restrict__ Wp,
    float* __restrict__ h) {
    __shared__ float Wt[DIN][D];          // Wt[j][k] = Wp[k][j]
    int tid = threadIdx.x;
    for (int i = tid; i < D * DIN; i += 256) {
        int k = i >> 4, j = i & 15;
        Wt[j][k] = Wp[i];
    }
    __syncthreads();
    int warp = tid >> 5, lane = tid & 31;
    int k0 = lane * 4;
    float4 w[16];
#pragma unroll
    for (int j = 0; j < 16; j++) w[j] = *(const float4*)&Wt[j][k0];

    int base = blockIdx.x * 32 + warp * 4;   // 4 nodes per warp
#pragma unroll
    for (int nn = 0; nn < 4; nn++) {
        int i = base + nn;
        if (i >= N_NODES) return;
        float xv = x[i * DIN + (lane & 15)];
        float4 acc = make_float4(0.f, 0.f, 0.f, 0.f);
#pragma unroll
        for (int j = 0; j < 16; j++) {
            float xj = __shfl_sync(0xffffffffu, xv, j);
            acc.x += xj * w[j].x; acc.y += xj * w[j].y;
            acc.z += xj * w[j].z; acc.w += xj * w[j].w;
        }
        *(float4*)&h[i * D + k0] = acc;
    }
}

// ---------------- attention vectors: vr0=W0.T@ar0, vr1=W1.T@ar1, bvec=Wl2@bias -
__global__ __launch_bounds__(128) void attnvec_kernel(
    const float* __restrict__ Wg0, const float* __restrict__ ar0,
    const float* __restrict__ Wg1, const float* __restrict__ ar1,
    const float* __restrict__ Wl, const float* __restrict__ bias) {
    int k = threadIdx.x;
    float s0 = 0.f, s1 = 0.f, sb = 0.f;
    for (int j = 0; j < D; j++) {
        s0 += Wg0[j * D + k] * ar0[j];
        s1 += Wg1[j * D + k] * ar1[j];
        sb += Wl[k * (2 * D) + D + j] * bias[j];
    }
    g_vr0[k] = s0; g_vr1[k] = s1; g_bvec[k] = sb;
}

// ---------------- 3xTF32 mma building blocks ------------------------------------
#define SM_STRIDE 132
#define SMEM_TC ((64 + 128) * SM_STRIDE * 4)

__device__ __forceinline__ unsigned f2tf(float x) {
    unsigned r;
    asm("cvt.rna.tf32.f32 %0, %1;" : "=r"(r) : "f"(x));
    return r;
}

#define MMA_TF32(acc, a0, a1, a2, a3, b0, b1)                                   \
    asm volatile(                                                               \
        "mma.sync.aligned.m16n8k8.row.col.f32.tf32.tf32.f32 "                   \
        "{%0,%1,%2,%3},{%4,%5,%6,%7},{%8,%9},{%0,%1,%2,%3};"                    \
        : "+f"(acc[0]), "+f"(acc[1]), "+f"(acc[2]), "+f"(acc[3])                \
        : "r"(a0), "r"(a1), "r"(a2), "r"(a3), "r"(b0), "r"(b1))

// Core mma loop over the staged As/Bs tiles. Each warp: 32 rows x 32 cols.
__device__ __forceinline__ void mma_tile_compute(
    const float* As, const float* Bs, float acc[2][4][4],
    int wm, int wn, int qr, int qc)
{
#pragma unroll
    for (int mt = 0; mt < 2; mt++)
#pragma unroll
        for (int nt = 0; nt < 4; nt++)
#pragma unroll
            for (int j = 0; j < 4; j++) acc[mt][nt][j] = 0.f;

    for (int k0 = 0; k0 < 128; k0 += 8) {
        unsigned ahi[2][4], alo[2][4];
#pragma unroll
        for (int mt = 0; mt < 2; mt++) {
            int rb = wm * 32 + mt * 16 + qr;
            float x0 = As[rb * SM_STRIDE + k0 + qc];
            float x1 = As[(rb + 8) * SM_STRIDE + k0 + qc];
            float x2 = As[rb * SM_STRIDE + k0 + qc + 4];
            float x3 = As[(rb + 8) * SM_STRIDE + k0 + qc + 4];
            ahi[mt][0] = f2tf(x0); alo[mt][0] = __float_as_uint(x0 - __uint_as_float(ahi[mt][0]));
            ahi[mt][1] = f2tf(x1); alo[mt][1] = __float_as_uint(x1 - __uint_as_float(ahi[mt][1]));
            ahi[mt][2] = f2tf(x2); alo[mt][2] = __float_as_uint(x2 - __uint_as_float(ahi[mt][2]));
            ahi[mt][3] = f2tf(x3); alo[mt][3] = __float_as_uint(x3 - __uint_as_float(ahi[mt][3]));
        }
#pragma unroll
        for (int nt = 0; nt < 4; nt++) {
            int cb = wn * 32 + nt * 8 + qr;
            float y0 = Bs[cb * SM_STRIDE + k0 + qc];
            float y1 = Bs[cb * SM_STRIDE + k0 + qc + 4];
            unsigned bhi0 = f2tf(y0), bhi1 = f2tf(y1);
            unsigned blo0 = __float_as_uint(y0 - __uint_as_float(bhi0));
            unsigned blo1 = __float_as_uint(y1 - __uint_as_float(bhi1));
#pragma unroll
            for (int mt = 0; mt < 2; mt++) {
                MMA_TF32(acc[mt][nt], alo[mt][0], alo[mt][1], alo[mt][2], alo[mt][3], bhi0, bhi1);
                MMA_TF32(acc[mt][nt], ahi[mt][0], ahi[mt][1], ahi[mt][2], ahi[mt][3], blo0, blo1);
                MMA_TF32(acc[mt][nt], ahi[mt][0], ahi[mt][1], ahi[mt][2], ahi[mt][3], bhi0, bhi1);
            }
        }
    }
}

// ---------------- fused multi-weight GEMM: A staged once, up to 3 weights -------
__global__ __launch_bounds__(256, 2) void gemm_multi(
    const float* __restrict__ A,
    const float* __restrict__ W0, int ws0, float* __restrict__ C0,
    const float* __restrict__ W1, int ws1, float* __restrict__ C1,
    const float* __restrict__ W2, int ws2, float* __restrict__ C2,
    int nrows)
{
    extern __shared__ float sm[];
    float* As = sm;
    float* Bs = sm + 64 * SM_STRIDE;
    int tid = threadIdx.x;
    int row0 = blockIdx.x * 64;

    const float* Wlist[3] = {W0, W1, W2};
    int wslist[3] = {ws0, ws1, ws2};
    float* Clist[3] = {C0, C1, C2};

    for (int i = tid; i < 64 * 32; i += 256) {
        int r = i >> 5, c4 = (i & 31) * 4;
        int gr = row0 + r;
        float4 v = make_float4(0.f, 0.f, 0.f, 0.f);
        if (gr < nrows) v = *(const float4*)&A[(size_t)gr * D + c4];
        *(float4*)&As[r * SM_STRIDE + c4] = v;
    }
    {
        const float* W = Wlist[0];
        int ws = wslist[0];
        for (int i = tid; i < 128 * 32; i += 256) {
            int r = i >> 5, c4 = (i & 31) * 4;
            float4 v = *(const float4*)&W[(size_t)r * ws + c4];
            *(float4*)&Bs[r * SM_STRIDE + c4] = v;
        }
    }
    __syncthreads();

    int lane = tid & 31, wid = tid >> 5;
    int wm = wid & 1, wn = wid >> 1;
    int qr = lane >> 2, qc = lane & 3;

#pragma unroll 1
    for (int s = 0; s < 3; s++) {
        if (!Wlist[s]) break;
        float acc[2][4][4];
        mma_tile_compute(As, Bs, acc, wm, wn, qr, qc);
        __syncthreads();

        if (s + 1 < 3 && Wlist[s + 1]) {
            const float* W = Wlist[s + 1];
            int ws = wslist[s + 1];
            for (int i = tid; i < 128 * 32; i += 256) {
                int r = i >> 5, c4 = (i & 31) * 4;
                float4 v = *(const float4*)&W[(size_t)r * ws + c4];
                *(float4*)&Bs[r * SM_STRIDE + c4] = v;
            }
        }

        float* C = Clist[s];
#pragma unroll
        for (int mt = 0; mt < 2; mt++) {
#pragma unroll
            for (int half = 0; half < 2; half++) {
                int gr = row0 + wm * 32 + mt * 16 + qr + half * 8;
                if (gr >= nrows) continue;
#pragma unroll
                for (int nt = 0; nt < 4; nt++) {
                    int col = wn * 32 + nt * 8 + qc * 2;
                    float2 o = make_float2(acc[mt][nt][half * 2 + 0],
                                           acc[mt][nt][half * 2 + 1]);
                    *(float2*)&C[(size_t)gr * D + col] = o;
                }
            }
        }
        __syncthreads();
    }
}

// ---------------- fused output chain: nsteps x [relu(base+bvec+As@W.T)] --------
// Chain steps are row-local; intermediates stay in the smem As tile instead of
// doing global round-trips between launches. addMid is folded into As before
// step addIdx. initRelu=1 computes As = relu(preA + bvec) at staging (cell step0).
__global__ __launch_bounds__(256, 2) void chain_tc(
    const float* __restrict__ preA, int initRelu,
    const float* __restrict__ addMid, int addIdx, int nsteps,
    const float* __restrict__ base, const float* __restrict__ bvec,
    const float* __restrict__ W,
    float* __restrict__ C, int nrows)
{
    extern __shared__ float sm[];
    float* As = sm;                       // [64][SM_STRIDE]
    float* Bs = sm + 64 * SM_STRIDE;      // [128][SM_STRIDE]
    int tid = threadIdx.x;
    int row0 = blockIdx.x * 64;

    // stage W (Wl2, row stride 2D)
    for (int i = tid; i < 128 * 32; i += 256) {
        int r = i >> 5, c4 = (i & 31) * 4;
        float4 v = *(const float4*)&W[(size_t)r * (2 * D) + c4];
        *(float4*)&Bs[r * SM_STRIDE + c4] = v;
    }
    // stage initial As
    for (int i = tid; i < 64 * 32; i += 256) {
        int r = i >> 5, c4 = (i & 31) * 4;
        int gr = row0 + r;
        float4 v = make_float4(0.f, 0.f, 0.f, 0.f);
        if (gr < nrows) {
            v = *(const float4*)&preA[(size_t)gr * D + c4];
            if (initRelu) {
                float4 b = *(const float4*)&bvec[c4];
                v.x = fmaxf(v.x + b.x, 0.f); v.y = fmaxf(v.y + b.y, 0.f);
                v.z = fmaxf(v.z + b.z, 0.f); v.w = fmaxf(v.w + b.w, 0.f);
            }
        }
        *(float4*)&As[r * SM_STRIDE + c4] = v;
    }
    __syncthreads();

    int lane = tid & 31, wid = tid >> 5;
    int wm = wid & 1, wn = wid >> 1;
    int qr = lane >> 2, qc = lane & 3;

    // bvec values for this thread's epilogue columns (fixed across steps)
    float bv[4][2];
#pragma unroll
    for (int nt = 0; nt < 4; nt++) {
        int col = wn * 32 + nt * 8 + qc * 2;
        bv[nt][0] = bvec[col]; bv[nt][1] = bvec[col + 1];
    }

#pragma unroll 1
    for (int s = 0; s < nsteps; s++) {
        if (s == addIdx && addMid) {
            for (int i = tid; i < 64 * 32; i += 256) {
                int r = i >> 5, c4 = (i & 31) * 4;
                int gr = row0 + r;
                if (gr < nrows) {
                    float4 a = *(const float4*)&addMid[(size_t)gr * D + c4];
                    float4 v = *(float4*)&As[r * SM_STRIDE + c4];
                    v.x += a.x; v.y += a.y; v.z += a.z; v.w += a.w;
                    *(float4*)&As[r * SM_STRIDE + c4] = v;
                }
            }
            __syncthreads();
        }

        float acc[2][4][4];
        mma_tile_compute(As, Bs, acc, wm, wn, qr, qc);
        __syncthreads();   // done reading As; safe to overwrite

        bool last = (s == nsteps - 1);
#pragma unroll
        for (int mt = 0; mt < 2; mt++) {
#pragma unroll
            for (int half = 0; half < 2; half++) {
                int grl = wm * 32 + mt * 16 + qr + half * 8;
                int gr = row0 + grl;
                if (gr >= nrows) continue;
#pragma unroll
                for (int nt = 0; nt < 4; nt++) {
                    int col = wn * 32 + nt * 8 + qc * 2;
                    float2 b = *(const float2*)&base[(size_t)gr * D + col];
                    float v0 = fmaxf(acc[mt][nt][half * 2 + 0] + b.x + bv[nt][0], 0.f);
                    float v1 = fmaxf(acc[mt][nt][half * 2 + 1] + b.y + bv[nt][1], 0.f);
                    if (last) {
                        *(float2*)&C[(size_t)gr * D + col] = make_float2(v0, v1);
                    } else {
                        As[grl * SM_STRIDE + col]     = v0;
                        As[grl * SM_STRIDE + col + 1] = v1;
                    }
                }
            }
        }
        __syncthreads();   // As fully updated before next compute
    }
}

// ---------------- attention logits (el/er) per node -----------------------------
__global__ __launch_bounds__(256) void scores_net(
    const float* __restrict__ al1, const float* __restrict__ al2,
    const float* __restrict__ ar2) {
    int warp = threadIdx.x >> 5, lane = threadIdx.x & 31;
    int i = blockIdx.x * 8 + warp;
    if (i >= N_NODES) return;
    int o = i * D + lane * 4, c = lane * 4;
    float4 hn = *(const float4*)&g_hnet[o];
    float4 h1 = *(const float4*)&g_hs1[o];
    float4 h2 = *(const float4*)&g_hs2[o];
    float4 v0 = *(const float4*)&g_vr0[c];
    float4 a1 = *(const float4*)&al1[c];
    float4 a2 = *(const float4*)&al2[c];
    float4 r2 = *(const float4*)&ar2[c];
    float d0 = hn.x * v0.x + hn.y * v0.y + hn.z * v0.z + hn.w * v0.w;
    float d1 = h1.x * a1.x + h1.y * a1.y + h1.z * a1.z + h1.w * a1.w;
    float d2 = h2.x * a2.x + h2.y * a2.y + h2.z * a2.z + h2.w * a2.w;
    float d3 = h2.x * r2.x + h2.y * r2.y + h2.z * r2.z + h2.w * r2.w;
#pragma unroll
    for (int off = 16; off; off >>= 1) {
        d0 += __shfl_xor_sync(0xffffffffu, d0, off);
        d1 += __shfl_xor_sync(0xffffffffu, d1, off);
        d2 += __shfl_xor_sync(0xffffffffu, d2, off);
        d3 += __shfl_xor_sync(0xffffffffu, d3, off);
    }
    if (lane == 0) {
        g_er[0][i] = d0;
        g_el[1][i] = d1;
        g_el[2][i] = d2;
        g_er[2][i] = d3;
    }
}

__global__ __launch_bounds__(256) void scores_cell(const float* __restrict__ al0) {
    int warp = threadIdx.x >> 5, lane = threadIdx.x & 31;
    int i = blockIdx.x * 8 + warp;
    if (i >= N_NODES) return;
    int o = i * D + lane * 4, c = lane * 4;
    float4 h0 = *(const float4*)&g_hs0[o];
    float4 hc = *(const float4*)&g_hcell[o];
    float4 a0 = *(const float4*)&al0[c];
    float4 v1 = *(const float4*)&g_vr1[c];
    float d0 = h0.x * a0.x + h0.y * a0.y + h0.z * a0.z + h0.w * a0.w;
    float d1 = hc.x * v1.x + hc.y * v1.y + hc.z * v1.z + hc.w * v1.w;
#pragma unroll
    for (int off = 16; off; off >>= 1) {
        d0 += __shfl_xor_sync(0xffffffffu, d0, off);
        d1 += __shfl_xor_sync(0xffffffffu, d1, off);
    }
    if (lane == 0) {
        g_el[0][i] = d0;
        g_er[1][i] = d1;
    }
}

// ---------------- CSR build ------------------------------------------------------
__global__ __launch_bounds__(256) void count3_kernel(
    const int* __restrict__ dst0, const int* __restrict__ dst1,
    const int* __restrict__ dst2) {
    int e = blockIdx.x * blockDim.x + threadIdx.x;
    if (e >= N_EDGES) return;
    atomicAdd(&g_cnt[0][dst0[e]], 1);
    atomicAdd(&g_cnt[1][dst1[e]], 1);
    atomicAdd(&g_cnt[2][dst2[e]], 1);
}

__global__ __launch_bounds__(256) void scan_kernel() {
    int r = blockIdx.x;
    const int* cnt = g_cnt[r];
    int* rp = g_rowptr[r];
    __shared__ int part[256];
    int t = threadIdx.x;
    const int CH = 391;  // 256*391 >= 100000
    int base = t * CH;
    int s = 0;
    for (int j = 0; j < CH; j++) {
        int idx = base + j;
        if (idx < N_NODES) s += cnt[idx];
    }
    part[t] = s;
    __syncthreads();
    if (t == 0) {
        int acc = 0;
        for (int i = 0; i < 256; i++) { int v = part[i]; part[i] = acc; acc += v; }
        rp[N_NODES] = acc;
    }
    __syncthreads();
    int acc = part[t];
    for (int j = 0; j < CH; j++) {
        int idx = base + j;
        if (idx < N_NODES) { rp[idx] = acc; acc += cnt[idx]; }
    }
}

__global__ __launch_bounds__(256) void fill_kernel(
    const int* __restrict__ src, const int* __restrict__ dst, int rel) {
    int e = blockIdx.x * blockDim.x + threadIdx.x;
    if (e >= N_EDGES) return;
    int s = src[e], d = dst[e];
    float x = g_el[rel][s] + g_er[rel][d];
    x = x > 0.f ? x : 0.2f * x;           // leaky_relu
    float w = __expf(x);
    int pos = atomicAdd(&g_cursor[rel][d], 1);
    int idx = g_rowptr[rel][d] + pos;
    g_csrc[rel][idx] = s;
    g_cw[rel][idx] = w;
}

// ---------------- atomic-free aggregation: agg[d] = sum(w*hs[src]) / sum(w) -----
__global__ __launch_bounds__(256) void aggregate_kernel(
    const float* __restrict__ hs, float* __restrict__ agg, int rel) {
    int warp = threadIdx.x >> 5, lane = threadIdx.x & 31;
    int i = blockIdx.x * 8 + warp;
    if (i >= N_NODES) return;
    int start = g_rowptr[rel][i];
    int end = g_rowptr[rel][i + 1];
    const float4* hv = (const float4*)hs;
    float4 acc = make_float4(0.f, 0.f, 0.f, 0.f);
    float wsum = 0.f;
    for (int t = start; t < end; t++) {
        int s = g_csrc[rel][t];
        float w = g_cw[rel][t];
        float4 v = hv[(size_t)s * 32 + lane];
        acc.x += w * v.x; acc.y += w * v.y; acc.z += w * v.z; acc.w += w * v.w;
        wsum += w;
    }
    float4 o = make_float4(0.f, 0.f, 0.f, 0.f);
    if (end > start) {
        float inv = 1.f / wsum;
        o = make_float4(acc.x * inv, acc.y * inv, acc.z * inv, acc.w * inv);
    }
    ((float4*)agg)[(size_t)i * 32 + lane] = o;
}

// ---------------- host orchestration (3-stream fork/join DAG) -------------------
extern "C" void kernel_launch(void* const* d_in, const int* in_sizes, int n_in,
                              void* d_out, int out_size) {
    const float* x_net   = (const float*)d_in[0];
    const float* x_cell  = (const float*)d_in[1];
    const float* Wp_net  = (const float*)d_in[2];
    const float* Wp_cell = (const float*)d_in[3];
    const float* Wg0 = (const float*)d_in[4];
    const float* al0 = (const float*)d_in[5];
    const float* ar0 = (const float*)d_in[6];
    const float* Wg1 = (const float*)d_in[7];
    const float* al1 = (const float*)d_in[8];
    const float* ar1 = (const float*)d_in[9];
    const float* Wg2 = (const float*)d_in[10];
    const float* al2 = (const float*)d_in[11];
    const float* ar2 = (const float*)d_in[12];
    const float* Wl   = (const float*)d_in[13];
    const float* bias = (const float*)d_in[14];
    const int* src0 = (const int*)d_in[15];
    const int* dst0 = (const int*)d_in[16];
    const int* src1 = (const int*)d_in[17];
    const int* dst1 = (const int*)d_in[18];
    const int* src2 = (const int*)d_in[19];
    const int* dst2 = (const int*)d_in[20];
    float* out = (float*)d_out;

    float *hnet, *hcell, *hs0, *hs1, *hs2, *bnet, *bcell;
    float *agg0, *agg1, *agg2, *bvec;
    int *cnt, *cursor;
    cudaGetSymbolAddress((void**)&hnet,  g_hnet);
    cudaGetSymbolAddress((void**)&hcell, g_hcell);
    cudaGetSymbolAddress((void**)&hs0,   g_hs0);
    cudaGetSymbolAddress((void**)&hs1,   g_hs1);
    cudaGetSymbolAddress((void**)&hs2,   g_hs2);
    cudaGetSymbolAddress((void**)&bnet,  g_bnet);
    cudaGetSymbolAddress((void**)&bcell, g_bcell);
    cudaGetSymbolAddress((void**)&agg0,  g_agg0);
    cudaGetSymbolAddress((void**)&agg1,  g_agg1);
    cudaGetSymbolAddress((void**)&agg2,  g_agg2);
    cudaGetSymbolAddress((void**)&bvec,  g_bvec);
    cudaGetSymbolAddress((void**)&cnt,   g_cnt);
    cudaGetSymbolAddress((void**)&cursor, g_cursor);

    static cudaStream_t sA = 0, sB = 0, sC = 0;
    static cudaEvent_t evFork, eA1, eB1, eC1, eC2, eA3, eB3;
    static int init_done = 0;
    if (!init_done) {
        cudaFuncSetAttribute(gemm_multi, cudaFuncAttributeMaxDynamicSharedMemorySize, SMEM_TC);
        cudaFuncSetAttribute(chain_tc,   cudaFuncAttributeMaxDynamicSharedMemorySize, SMEM_TC);
        cudaStreamCreateWithFlags(&sA, cudaStreamNonBlocking);
        cudaStreamCreateWithFlags(&sB, cudaStreamNonBlocking);
        cudaStreamCreateWithFlags(&sC, cudaStreamNonBlocking);
        cudaEventCreateWithFlags(&evFork, cudaEventDisableTiming);
        cudaEventCreateWithFlags(&eA1, cudaEventDisableTiming);
        cudaEventCreateWithFlags(&eB1, cudaEventDisableTiming);
        cudaEventCreateWithFlags(&eC1, cudaEventDisableTiming);
        cudaEventCreateWithFlags(&eC2, cudaEventDisableTiming);
        cudaEventCreateWithFlags(&eA3, cudaEventDisableTiming);
        cudaEventCreateWithFlags(&eB3, cudaEventDisableTiming);
        init_done = 1;
    }

    const int GN = (N_NODES + 7) / 8;        // warp-per-node kernels
    const int GP = (N_NODES + 31) / 32;      // proj: 4 nodes/warp
    const int GT = (N_NODES + 63) / 64;      // tensor gemm tiles (BM=64)
    const int GE = (N_EDGES + 255) / 256;
    const float* Wl2 = Wl + D;               // Wl[:, 128:], row stride 2*D

    // ---- pre-fork (origin stream): tiny attention-vector GEMVs ----
    attnvec_kernel<<<1, D, 0, 0>>>(Wg0, ar0, Wg1, ar1, Wl, bias);
    cudaEventRecord(evFork, 0);
    cudaStreamWaitEvent(sA, evFork, 0);
    cudaStreamWaitEvent(sB, evFork, 0);
    cudaStreamWaitEvent(sC, evFork, 0);

    // ---- branch C: CSR skeleton (independent of features) ----
    cudaMemsetAsync(cnt,    0, sizeof(int) * 3 * N_NODES, sC);
    cudaMemsetAsync(cursor, 0, sizeof(int) * 3 * N_NODES, sC);
    count3_kernel<<<GE, 256, 0, sC>>>(dst0, dst1, dst2);
    scan_kernel<<<3, 256, 0, sC>>>();
    cudaEventRecord(eC1, sC);

    // ---- branch A: net-side features (fused 3-weight GEMM) ----
    proj_kernel<<<GP, 256, 0, sA>>>(x_net, Wp_net, hnet);
    gemm_multi<<<GT, 256, SMEM_TC, sA>>>(hnet,
        Wg1, D, hs1, Wg2, D, hs2, Wl, 2 * D, bnet, N_NODES);
    scores_net<<<GN, 256, 0, sA>>>(al1, al2, ar2);
    cudaEventRecord(eA1, sA);

    // ---- branch B: cell-side features (fused 2-weight GEMM) ----
    proj_kernel<<<GP, 256, 0, sB>>>(x_cell, Wp_cell, hcell);
    gemm_multi<<<GT, 256, SMEM_TC, sB>>>(hcell,
        Wg0, D, hs0, Wl, 2 * D, bcell, nullptr, 0, nullptr, N_NODES);
    scores_cell<<<GN, 256, 0, sB>>>(al0);
    cudaEventRecord(eB1, sB);

    // ---- join J1: scores + CSR skeleton complete everywhere ----
    cudaStreamWaitEvent(sA, eB1, 0); cudaStreamWaitEvent(sA, eC1, 0);
    cudaStreamWaitEvent(sB, eA1, 0); cudaStreamWaitEvent(sB, eC1, 0);
    cudaStreamWaitEvent(sC, eA1, 0); cudaStreamWaitEvent(sC, eB1, 0);

    // ---- per-relation fill + aggregate, one relation per stream ----
    fill_kernel<<<GE, 256, 0, sA>>>(src0, dst0, 0);
    aggregate_kernel<<<GN, 256, 0, sA>>>(hs0, agg0, 0);
    fill_kernel<<<GE, 256, 0, sB>>>(src1, dst1, 1);
    aggregate_kernel<<<GN, 256, 0, sB>>>(hs1, agg1, 1);
    fill_kernel<<<GE, 256, 0, sC>>>(src2, dst2, 2);
    aggregate_kernel<<<GN, 256, 0, sC>>>(hs2, agg2, 2);
    cudaEventRecord(eC2, sC);

    // ---- branch A: fused net output chain (3 steps; agg2 added before step 2) --
    cudaStreamWaitEvent(sA, eC2, 0);
    chain_tc<<<GT, 256, SMEM_TC, sA>>>(agg0, 0, agg2, 2, 3,
                                       bnet, bvec, Wl2, out, N_NODES);
    cudaEventRecord(eA3, sA);

    // ---- branch B: fused cell output chain (2 steps; init relu; agg1 @ step 0) -
    chain_tc<<<GT, 256, SMEM_TC, sB>>>(bcell, 1, agg1, 0, 2,
                                       bcell, bvec, Wl2, out + ND, N_NODES);
    cudaEventRecord(eB3, sB);

    // ---- join back to origin stream ----
    cudaStreamWaitEvent(0, eA3, 0);
    cudaStreamWaitEvent(0, eB3, 0);
}

// round 12
// speedup vs baseline: 1.8754x; 1.0472x over previous
#include <cuda_runtime.h>

#define N_NODES 100000
#define N_EDGES 600000
#define D 128
#define DIN 16
#define ND (N_NODES * D)

// ---------------- scratch (static __device__ arrays; no allocs) ----------------
__device__ float g_hnet[ND], g_hcell[ND];                 // projected features
__device__ float g_hs0[ND], g_hs1[ND], g_hs2[ND];         // h_src per relation
__device__ float g_bnet[ND], g_bcell[ND];                 // feat @ Wl1.T
__device__ float g_agg0[ND], g_agg1[ND], g_agg2[ND];      // normalized GAT outputs
__device__ float g_el[3][N_NODES], g_er[3][N_NODES];
__device__ float g_vr0[D], g_vr1[D], g_bvec[D];
__device__ int   g_cnt[3][N_NODES];
__device__ int   g_rowptr[3][N_NODES + 1];
__device__ int   g_cursor[3][N_NODES];
__device__ int   g_csrc[3][N_EDGES];
__device__ float g_cw[3][N_EDGES];

// ---------------- feature projection: h = x @ Wp.T  ([N,16] -> [N,128]) --------
__global__ __launch_bounds__(256) void proj_kernel(
    const float* __restrict__ x, const float* __restrict__ Wp,
    float* __restrict__ h) {
    __shared__ float Wt[DIN][D];          // Wt[j][k] = Wp[k][j]
    int tid = threadIdx.x;
    for (int i = tid; i < D * DIN; i += 256) {
        int k = i >> 4, j = i & 15;
        Wt[j][k] = Wp[i];
    }
    __syncthreads();
    int warp = tid >> 5, lane = tid & 31;
    int k0 = lane * 4;
    float4 w[16];
#pragma unroll
    for (int j = 0; j < 16; j++) w[j] = *(const float4*)&Wt[j][k0];

    int base = blockIdx.x * 32 + warp * 4;   // 4 nodes per warp
#pragma unroll
    for (int nn = 0; nn < 4; nn++) {
        int i = base + nn;
        if (i >= N_NODES) return;
        float xv = x[i * DIN + (lane & 15)];
        float4 acc = make_float4(0.f, 0.f, 0.f, 0.f);
#pragma unroll
        for (int j = 0; j < 16; j++) {
            float xj = __shfl_sync(0xffffffffu, xv, j);
            acc.x += xj * w[j].x; acc.y += xj * w[j].y;
            acc.z += xj * w[j].z; acc.w += xj * w[j].w;
        }
        *(float4*)&h[i * D + k0] = acc;
    }
}

// ---------------- attention vectors (3 blocks: vr0, vr1, bvec) ------------------
__global__ __launch_bounds__(128) void attnvec3_kernel(
    const float* __restrict__ Wg0, const float* __restrict__ ar0,
    const float* __restrict__ Wg1, const float* __restrict__ ar1,
    const float* __restrict__ Wl, const float* __restrict__ bias) {
    int k = threadIdx.x;
    int which = blockIdx.x;
    float s = 0.f;
    if (which == 0) {
#pragma unroll 8
        for (int j = 0; j < D; j++) s += Wg0[j * D + k] * ar0[j];
        g_vr0[k] = s;
    } else if (which == 1) {
#pragma unroll 8
        for (int j = 0; j < D; j++) s += Wg1[j * D + k] * ar1[j];
        g_vr1[k] = s;
    } else {
#pragma unroll 8
        for (int j = 0; j < D; j++) s += Wl[k * (2 * D) + D + j] * bias[j];
        g_bvec[k] = s;
    }
}

// ---------------- 3xTF32 mma building blocks ------------------------------------
#define SM_STRIDE 132
#define SMEM_TC ((64 + 128) * SM_STRIDE * 4)

__device__ __forceinline__ unsigned f2tf(float x) {
    unsigned r;
    asm("cvt.rna.tf32.f32 %0, %1;" : "=r"(r) : "f"(x));
    return r;
}

#define MMA_TF32(acc, a0, a1, a2, a3, b0, b1)                                   \
    asm volatile(                                                               \
        "mma.sync.aligned.m16n8k8.row.col.f32.tf32.tf32.f32 "                   \
        "{%0,%1,%2,%3},{%4,%5,%6,%7},{%8,%9},{%0,%1,%2,%3};"                    \
        : "+f"(acc[0]), "+f"(acc[1]), "+f"(acc[2]), "+f"(acc[3])                \
        : "r"(a0), "r"(a1), "r"(a2), "r"(a3), "r"(b0), "r"(b1))

// Core mma loop over the staged As/Bs tiles. Each warp: 32 rows x 32 cols.
__device__ __forceinline__ void mma_tile_compute(
    const float* As, const float* Bs, float acc[2][4][4],
    int wm, int wn, int qr, int qc)
{
#pragma unroll
    for (int mt = 0; mt < 2; mt++)
#pragma unroll
        for (int nt = 0; nt < 4; nt++)
#pragma unroll
            for (int j = 0; j < 4; j++) acc[mt][nt][j] = 0.f;

    for (int k0 = 0; k0 < 128; k0 += 8) {
        unsigned ahi[2][4], alo[2][4];
#pragma unroll
        for (int mt = 0; mt < 2; mt++) {
            int rb = wm * 32 + mt * 16 + qr;
            float x0 = As[rb * SM_STRIDE + k0 + qc];
            float x1 = As[(rb + 8) * SM_STRIDE + k0 + qc];
            float x2 = As[rb * SM_STRIDE + k0 + qc + 4];
            float x3 = As[(rb + 8) * SM_STRIDE + k0 + qc + 4];
            ahi[mt][0] = f2tf(x0); alo[mt][0] = __float_as_uint(x0 - __uint_as_float(ahi[mt][0]));
            ahi[mt][1] = f2tf(x1); alo[mt][1] = __float_as_uint(x1 - __uint_as_float(ahi[mt][1]));
            ahi[mt][2] = f2tf(x2); alo[mt][2] = __float_as_uint(x2 - __uint_as_float(ahi[mt][2]));
            ahi[mt][3] = f2tf(x3); alo[mt][3] = __float_as_uint(x3 - __uint_as_float(ahi[mt][3]));
        }
#pragma unroll
        for (int nt = 0; nt < 4; nt++) {
            int cb = wn * 32 + nt * 8 + qr;
            float y0 = Bs[cb * SM_STRIDE + k0 + qc];
            float y1 = Bs[cb * SM_STRIDE + k0 + qc + 4];
            unsigned bhi0 = f2tf(y0), bhi1 = f2tf(y1);
            unsigned blo0 = __float_as_uint(y0 - __uint_as_float(bhi0));
            unsigned blo1 = __float_as_uint(y1 - __uint_as_float(bhi1));
#pragma unroll
            for (int mt = 0; mt < 2; mt++) {
                MMA_TF32(acc[mt][nt], alo[mt][0], alo[mt][1], alo[mt][2], alo[mt][3], bhi0, bhi1);
                MMA_TF32(acc[mt][nt], ahi[mt][0], ahi[mt][1], ahi[mt][2], ahi[mt][3], blo0, blo1);
                MMA_TF32(acc[mt][nt], ahi[mt][0], ahi[mt][1], ahi[mt][2], ahi[mt][3], bhi0, bhi1);
            }
        }
    }
}

// ---------------- fused multi-weight GEMM: A staged once, up to 3 weights -------
__global__ __launch_bounds__(256, 2) void gemm_multi(
    const float* __restrict__ A,
    const float* __restrict__ W0, int ws0, float* __restrict__ C0,
    const float* __restrict__ W1, int ws1, float* __restrict__ C1,
    const float* __restrict__ W2, int ws2, float* __restrict__ C2,
    int nrows)
{
    extern __shared__ float sm[];
    float* As = sm;
    float* Bs = sm + 64 * SM_STRIDE;
    int tid = threadIdx.x;
    int row0 = blockIdx.x * 64;

    const float* Wlist[3] = {W0, W1, W2};
    int wslist[3] = {ws0, ws1, ws2};
    float* Clist[3] = {C0, C1, C2};

    for (int i = tid; i < 64 * 32; i += 256) {
        int r = i >> 5, c4 = (i & 31) * 4;
        int gr = row0 + r;
        float4 v = make_float4(0.f, 0.f, 0.f, 0.f);
        if (gr < nrows) v = *(const float4*)&A[(size_t)gr * D + c4];
        *(float4*)&As[r * SM_STRIDE + c4] = v;
    }
    {
        const float* W = Wlist[0];
        int ws = wslist[0];
        for (int i = tid; i < 128 * 32; i += 256) {
            int r = i >> 5, c4 = (i & 31) * 4;
            float4 v = *(const float4*)&W[(size_t)r * ws + c4];
            *(float4*)&Bs[r * SM_STRIDE + c4] = v;
        }
    }
    __syncthreads();

    int lane = tid & 31, wid = tid >> 5;
    int wm = wid & 1, wn = wid >> 1;
    int qr = lane >> 2, qc = lane & 3;

#pragma unroll 1
    for (int s = 0; s < 3; s++) {
        if (!Wlist[s]) break;
        float acc[2][4][4];
        mma_tile_compute(As, Bs, acc, wm, wn, qr, qc);
        __syncthreads();

        if (s + 1 < 3 && Wlist[s + 1]) {
            const float* W = Wlist[s + 1];
            int ws = wslist[s + 1];
            for (int i = tid; i < 128 * 32; i += 256) {
                int r = i >> 5, c4 = (i & 31) * 4;
                float4 v = *(const float4*)&W[(size_t)r * ws + c4];
                *(float4*)&Bs[r * SM_STRIDE + c4] = v;
            }
        }

        float* C = Clist[s];
#pragma unroll
        for (int mt = 0; mt < 2; mt++) {
#pragma unroll
            for (int half = 0; half < 2; half++) {
                int gr = row0 + wm * 32 + mt * 16 + qr + half * 8;
                if (gr >= nrows) continue;
#pragma unroll
                for (int nt = 0; nt < 4; nt++) {
                    int col = wn * 32 + nt * 8 + qc * 2;
                    float2 o = make_float2(acc[mt][nt][half * 2 + 0],
                                           acc[mt][nt][half * 2 + 1]);
                    *(float2*)&C[(size_t)gr * D + col] = o;
                }
            }
        }
        __syncthreads();
    }
}

// ---------------- fused output chain: nsteps x [relu(base+bvec+As@W.T)] --------
__global__ __launch_bounds__(256, 2) void chain_tc(
    const float* __restrict__ preA, int initRelu,
    const float* __restrict__ addMid, int addIdx, int nsteps,
    const float* __restrict__ base, const float* __restrict__ bvec,
    const float* __restrict__ W,
    float* __restrict__ C, int nrows)
{
    extern __shared__ float sm[];
    float* As = sm;                       // [64][SM_STRIDE]
    float* Bs = sm + 64 * SM_STRIDE;      // [128][SM_STRIDE]
    int tid = threadIdx.x;
    int row0 = blockIdx.x * 64;

    for (int i = tid; i < 128 * 32; i += 256) {
        int r = i >> 5, c4 = (i & 31) * 4;
        float4 v = *(const float4*)&W[(size_t)r * (2 * D) + c4];
        *(float4*)&Bs[r * SM_STRIDE + c4] = v;
    }
    for (int i = tid; i < 64 * 32; i += 256) {
        int r = i >> 5, c4 = (i & 31) * 4;
        int gr = row0 + r;
        float4 v = make_float4(0.f, 0.f, 0.f, 0.f);
        if (gr < nrows) {
            v = *(const float4*)&preA[(size_t)gr * D + c4];
            if (initRelu) {
                float4 b = *(const float4*)&bvec[c4];
                v.x = fmaxf(v.x + b.x, 0.f); v.y = fmaxf(v.y + b.y, 0.f);
                v.z = fmaxf(v.z + b.z, 0.f); v.w = fmaxf(v.w + b.w, 0.f);
            }
        }
        *(float4*)&As[r * SM_STRIDE + c4] = v;
    }
    __syncthreads();

    int lane = tid & 31, wid = tid >> 5;
    int wm = wid & 1, wn = wid >> 1;
    int qr = lane >> 2, qc = lane & 3;

    float bv[4][2];
#pragma unroll
    for (int nt = 0; nt < 4; nt++) {
        int col = wn * 32 + nt * 8 + qc * 2;
        bv[nt][0] = bvec[col]; bv[nt][1] = bvec[col + 1];
    }

#pragma unroll 1
    for (int s = 0; s < nsteps; s++) {
        if (s == addIdx && addMid) {
            for (int i = tid; i < 64 * 32; i += 256) {
                int r = i >> 5, c4 = (i & 31) * 4;
                int gr = row0 + r;
                if (gr < nrows) {
                    float4 a = *(const float4*)&addMid[(size_t)gr * D + c4];
                    float4 v = *(float4*)&As[r * SM_STRIDE + c4];
                    v.x += a.x; v.y += a.y; v.z += a.z; v.w += a.w;
                    *(float4*)&As[r * SM_STRIDE + c4] = v;
                }
            }
            __syncthreads();
        }

        float acc[2][4][4];
        mma_tile_compute(As, Bs, acc, wm, wn, qr, qc);
        __syncthreads();

        bool last = (s == nsteps - 1);
#pragma unroll
        for (int mt = 0; mt < 2; mt++) {
#pragma unroll
            for (int half = 0; half < 2; half++) {
                int grl = wm * 32 + mt * 16 + qr + half * 8;
                int gr = row0 + grl;
                if (gr >= nrows) continue;
#pragma unroll
                for (int nt = 0; nt < 4; nt++) {
                    int col = wn * 32 + nt * 8 + qc * 2;
                    float2 b = *(const float2*)&base[(size_t)gr * D + col];
                    float v0 = fmaxf(acc[mt][nt][half * 2 + 0] + b.x + bv[nt][0], 0.f);
                    float v1 = fmaxf(acc[mt][nt][half * 2 + 1] + b.y + bv[nt][1], 0.f);
                    if (last) {
                        *(float2*)&C[(size_t)gr * D + col] = make_float2(v0, v1);
                    } else {
                        As[grl * SM_STRIDE + col]     = v0;
                        As[grl * SM_STRIDE + col + 1] = v1;
                    }
                }
            }
        }
        __syncthreads();
    }
}

// ---------------- attention logits (el/er) per node -----------------------------
__global__ __launch_bounds__(256) void scores_net(
    const float* __restrict__ al1, const float* __restrict__ al2,
    const float* __restrict__ ar2) {
    int warp = threadIdx.x >> 5, lane = threadIdx.x & 31;
    int i = blockIdx.x * 8 + warp;
    if (i >= N_NODES) return;
    int o = i * D + lane * 4, c = lane * 4;
    float4 hn = *(const float4*)&g_hnet[o];
    float4 h1 = *(const float4*)&g_hs1[o];
    float4 h2 = *(const float4*)&g_hs2[o];
    float4 v0 = *(const float4*)&g_vr0[c];
    float4 a1 = *(const float4*)&al1[c];
    float4 a2 = *(const float4*)&al2[c];
    float4 r2 = *(const float4*)&ar2[c];
    float d0 = hn.x * v0.x + hn.y * v0.y + hn.z * v0.z + hn.w * v0.w;
    float d1 = h1.x * a1.x + h1.y * a1.y + h1.z * a1.z + h1.w * a1.w;
    float d2 = h2.x * a2.x + h2.y * a2.y + h2.z * a2.z + h2.w * a2.w;
    float d3 = h2.x * r2.x + h2.y * r2.y + h2.z * r2.z + h2.w * r2.w;
#pragma unroll
    for (int off = 16; off; off >>= 1) {
        d0 += __shfl_xor_sync(0xffffffffu, d0, off);
        d1 += __shfl_xor_sync(0xffffffffu, d1, off);
        d2 += __shfl_xor_sync(0xffffffffu, d2, off);
        d3 += __shfl_xor_sync(0xffffffffu, d3, off);
    }
    if (lane == 0) {
        g_er[0][i] = d0;
        g_el[1][i] = d1;
        g_el[2][i] = d2;
        g_er[2][i] = d3;
    }
}

__global__ __launch_bounds__(256) void scores_cell(const float* __restrict__ al0) {
    int warp = threadIdx.x >> 5, lane = threadIdx.x & 31;
    int i = blockIdx.x * 8 + warp;
    if (i >= N_NODES) return;
    int o = i * D + lane * 4, c = lane * 4;
    float4 h0 = *(const float4*)&g_hs0[o];
    float4 hc = *(const float4*)&g_hcell[o];
    float4 a0 = *(const float4*)&al0[c];
    float4 v1 = *(const float4*)&g_vr1[c];
    float d0 = h0.x * a0.x + h0.y * a0.y + h0.z * a0.z + h0.w * a0.w;
    float d1 = hc.x * v1.x + hc.y * v1.y + hc.z * v1.z + hc.w * v1.w;
#pragma unroll
    for (int off = 16; off; off >>= 1) {
        d0 += __shfl_xor_sync(0xffffffffu, d0, off);
        d1 += __shfl_xor_sync(0xffffffffu, d1, off);
    }
    if (lane == 0) {
        g_el[0][i] = d0;
        g_er[1][i] = d1;
    }
}

// ---------------- CSR build ------------------------------------------------------
__global__ __launch_bounds__(256) void count3_kernel(
    const int* __restrict__ dst0, const int* __restrict__ dst1,
    const int* __restrict__ dst2) {
    int e = blockIdx.x * blockDim.x + threadIdx.x;
    if (e >= N_EDGES) return;
    atomicAdd(&g_cnt[0][dst0[e]], 1);
    atomicAdd(&g_cnt[1][dst1[e]], 1);
    atomicAdd(&g_cnt[2][dst2[e]], 1);
}

__global__ __launch_bounds__(256) void scan_kernel() {
    int r = blockIdx.x;
    const int* cnt = g_cnt[r];
    int* rp = g_rowptr[r];
    __shared__ int part[256];
    int t = threadIdx.x;
    const int CH = 391;  // 256*391 >= 100000
    int base = t * CH;
    int s = 0;
    for (int j = 0; j < CH; j++) {
        int idx = base + j;
        if (idx < N_NODES) s += cnt[idx];
    }
    part[t] = s;
    __syncthreads();
    if (t == 0) {
        int acc = 0;
        for (int i = 0; i < 256; i++) { int v = part[i]; part[i] = acc; acc += v; }
        rp[N_NODES] = acc;
    }
    __syncthreads();
    int acc = part[t];
    for (int j = 0; j < CH; j++) {
        int idx = base + j;
        if (idx < N_NODES) { rp[idx] = acc; acc += cnt[idx]; }
    }
}

// fills for all 3 relations in one launch (grid.y = rel)
__global__ __launch_bounds__(256) void fill3_kernel(
    const int* __restrict__ src0, const int* __restrict__ dst0,
    const int* __restrict__ src1, const int* __restrict__ dst1,
    const int* __restrict__ src2, const int* __restrict__ dst2) {
    int rel = blockIdx.y;
    const int* src = (rel == 0) ? src0 : (rel == 1) ? src1 : src2;
    const int* dst = (rel == 0) ? dst0 : (rel == 1) ? dst1 : dst2;
    int e = blockIdx.x * blockDim.x + threadIdx.x;
    if (e >= N_EDGES) return;
    int s = src[e], d = dst[e];
    float x = g_el[rel][s] + g_er[rel][d];
    x = x > 0.f ? x : 0.2f * x;           // leaky_relu
    float w = __expf(x);
    int pos = atomicAdd(&g_cursor[rel][d], 1);
    int idx = g_rowptr[rel][d] + pos;
    g_csrc[rel][idx] = s;
    g_cw[rel][idx] = w;
}

// ---------------- aggregation, all rels, 4-way edge-unrolled gathers ------------
__global__ __launch_bounds__(256) void aggregate3_kernel(
    const float* __restrict__ hsA, const float* __restrict__ hsB,
    const float* __restrict__ hsC,
    float* __restrict__ aggA, float* __restrict__ aggB, float* __restrict__ aggC) {
    int rel = blockIdx.y;
    const float* hs = (rel == 0) ? hsA : (rel == 1) ? hsB : hsC;
    float* agg = (rel == 0) ? aggA : (rel == 1) ? aggB : aggC;
    int warp = threadIdx.x >> 5, lane = threadIdx.x & 31;
    int i = blockIdx.x * 8 + warp;
    if (i >= N_NODES) return;
    int start = g_rowptr[rel][i];
    int end = g_rowptr[rel][i + 1];
    const float4* hv = (const float4*)hs;
    const int* cs = g_csrc[rel];
    const float* cw = g_cw[rel];
    float4 acc = make_float4(0.f, 0.f, 0.f, 0.f);
    float wsum = 0.f;
    int t = start;
    for (; t + 4 <= end; t += 4) {
        int s0 = cs[t], s1 = cs[t + 1], s2 = cs[t + 2], s3 = cs[t + 3];
        float w0 = cw[t], w1 = cw[t + 1], w2 = cw[t + 2], w3 = cw[t + 3];
        float4 v0 = hv[(size_t)s0 * 32 + lane];
        float4 v1 = hv[(size_t)s1 * 32 + lane];
        float4 v2 = hv[(size_t)s2 * 32 + lane];
        float4 v3 = hv[(size_t)s3 * 32 + lane];
        acc.x += w0 * v0.x + w1 * v1.x + w2 * v2.x + w3 * v3.x;
        acc.y += w0 * v0.y + w1 * v1.y + w2 * v2.y + w3 * v3.y;
        acc.z += w0 * v0.z + w1 * v1.z + w2 * v2.z + w3 * v3.z;
        acc.w += w0 * v0.w + w1 * v1.w + w2 * v2.w + w3 * v3.w;
        wsum += w0 + w1 + w2 + w3;
    }
    for (; t < end; t++) {
        int s = cs[t];
        float w = cw[t];
        float4 v = hv[(size_t)s * 32 + lane];
        acc.x += w * v.x; acc.y += w * v.y; acc.z += w * v.z; acc.w += w * v.w;
        wsum += w;
    }
    float4 o = make_float4(0.f, 0.f, 0.f, 0.f);
    if (end > start) {
        float inv = 1.f / wsum;
        o = make_float4(acc.x * inv, acc.y * inv, acc.z * inv, acc.w * inv);
    }
    ((float4*)agg)[(size_t)i * 32 + lane] = o;
}

// ---------------- host orchestration (3-stream fork/join DAG) -------------------
extern "C" void kernel_launch(void* const* d_in, const int* in_sizes, int n_in,
                              void* d_out, int out_size) {
    const float* x_net   = (const float*)d_in[0];
    const float* x_cell  = (const float*)d_in[1];
    const float* Wp_net  = (const float*)d_in[2];
    const float* Wp_cell = (const float*)d_in[3];
    const float* Wg0 = (const float*)d_in[4];
    const float* al0 = (const float*)d_in[5];
    const float* ar0 = (const float*)d_in[6];
    const float* Wg1 = (const float*)d_in[7];
    const float* al1 = (const float*)d_in[8];
    const float* ar1 = (const float*)d_in[9];
    const float* Wg2 = (const float*)d_in[10];
    const float* al2 = (const float*)d_in[11];
    const float* ar2 = (const float*)d_in[12];
    const float* Wl   = (const float*)d_in[13];
    const float* bias = (const float*)d_in[14];
    const int* src0 = (const int*)d_in[15];
    const int* dst0 = (const int*)d_in[16];
    const int* src1 = (const int*)d_in[17];
    const int* dst1 = (const int*)d_in[18];
    const int* src2 = (const int*)d_in[19];
    const int* dst2 = (const int*)d_in[20];
    float* out = (float*)d_out;

    float *hnet, *hcell, *hs0, *hs1, *hs2, *bnet, *bcell;
    float *agg0, *agg1, *agg2, *bvec;
    int *cnt, *cursor;
    cudaGetSymbolAddress((void**)&hnet,  g_hnet);
    cudaGetSymbolAddress((void**)&hcell, g_hcell);
    cudaGetSymbolAddress((void**)&hs0,   g_hs0);
    cudaGetSymbolAddress((void**)&hs1,   g_hs1);
    cudaGetSymbolAddress((void**)&hs2,   g_hs2);
    cudaGetSymbolAddress((void**)&bnet,  g_bnet);
    cudaGetSymbolAddress((void**)&bcell, g_bcell);
    cudaGetSymbolAddress((void**)&agg0,  g_agg0);
    cudaGetSymbolAddress((void**)&agg1,  g_agg1);
    cudaGetSymbolAddress((void**)&agg2,  g_agg2);
    cudaGetSymbolAddress((void**)&bvec,  g_bvec);
    cudaGetSymbolAddress((void**)&cnt,   g_cnt);
    cudaGetSymbolAddress((void**)&cursor, g_cursor);

    static cudaStream_t sA = 0, sB = 0, sC = 0;
    static cudaEvent_t evFork, eC0, eA1, eB1, eC1, eAgg, eA3, eB3;
    static int init_done = 0;
    if (!init_done) {
        cudaFuncSetAttribute(gemm_multi, cudaFuncAttributeMaxDynamicSharedMemorySize, SMEM_TC);
        cudaFuncSetAttribute(chain_tc,   cudaFuncAttributeMaxDynamicSharedMemorySize, SMEM_TC);
        cudaStreamCreateWithFlags(&sA, cudaStreamNonBlocking);
        cudaStreamCreateWithFlags(&sB, cudaStreamNonBlocking);
        cudaStreamCreateWithFlags(&sC, cudaStreamNonBlocking);
        cudaEventCreateWithFlags(&evFork, cudaEventDisableTiming);
        cudaEventCreateWithFlags(&eC0, cudaEventDisableTiming);
        cudaEventCreateWithFlags(&eA1, cudaEventDisableTiming);
        cudaEventCreateWithFlags(&eB1, cudaEventDisableTiming);
        cudaEventCreateWithFlags(&eC1, cudaEventDisableTiming);
        cudaEventCreateWithFlags(&eAgg, cudaEventDisableTiming);
        cudaEventCreateWithFlags(&eA3, cudaEventDisableTiming);
        cudaEventCreateWithFlags(&eB3, cudaEventDisableTiming);
        init_done = 1;
    }

    const int GN = (N_NODES + 7) / 8;        // warp-per-node kernels
    const int GP = (N_NODES + 31) / 32;      // proj: 4 nodes/warp
    const int GT = (N_NODES + 63) / 64;      // tensor gemm tiles (BM=64)
    const int GE = (N_EDGES + 255) / 256;
    const float* Wl2 = Wl + D;               // Wl[:, 128:], row stride 2*D

    // ---- fork immediately (no serial prefix) ----
    cudaEventRecord(evFork, 0);
    cudaStreamWaitEvent(sA, evFork, 0);
    cudaStreamWaitEvent(sB, evFork, 0);
    cudaStreamWaitEvent(sC, evFork, 0);

    // ---- branch C: attention vectors + CSR skeleton ----
    attnvec3_kernel<<<3, 128, 0, sC>>>(Wg0, ar0, Wg1, ar1, Wl, bias);
    cudaEventRecord(eC0, sC);
    cudaMemsetAsync(cnt,    0, sizeof(int) * 3 * N_NODES, sC);
    cudaMemsetAsync(cursor, 0, sizeof(int) * 3 * N_NODES, sC);
    count3_kernel<<<GE, 256, 0, sC>>>(dst0, dst1, dst2);
    scan_kernel<<<3, 256, 0, sC>>>();
    cudaEventRecord(eC1, sC);

    // ---- branch A: net-side features (fused 3-weight GEMM) ----
    proj_kernel<<<GP, 256, 0, sA>>>(x_net, Wp_net, hnet);
    gemm_multi<<<GT, 256, SMEM_TC, sA>>>(hnet,
        Wg1, D, hs1, Wg2, D, hs2, Wl, 2 * D, bnet, N_NODES);
    cudaStreamWaitEvent(sA, eC0, 0);
    scores_net<<<GN, 256, 0, sA>>>(al1, al2, ar2);
    cudaEventRecord(eA1, sA);

    // ---- branch B: cell-side features (fused 2-weight GEMM) ----
    proj_kernel<<<GP, 256, 0, sB>>>(x_cell, Wp_cell, hcell);
    gemm_multi<<<GT, 256, SMEM_TC, sB>>>(hcell,
        Wg0, D, hs0, Wl, 2 * D, bcell, nullptr, 0, nullptr, N_NODES);
    cudaStreamWaitEvent(sB, eC0, 0);
    scores_cell<<<GN, 256, 0, sB>>>(al0);
    cudaEventRecord(eB1, sB);

    // ---- join J1 on sA: scores + CSR skeleton complete ----
    cudaStreamWaitEvent(sA, eB1, 0);
    cudaStreamWaitEvent(sA, eC1, 0);

    // ---- single big fill + single big aggregate (device-saturating) ----
    dim3 gfill(GE, 3);
    fill3_kernel<<<gfill, 256, 0, sA>>>(src0, dst0, src1, dst1, src2, dst2);
    dim3 gagg(GN, 3);
    aggregate3_kernel<<<gagg, 256, 0, sA>>>(hs0, hs1, hs2, agg0, agg1, agg2);
    cudaEventRecord(eAgg, sA);

    // ---- output chains in parallel ----
    chain_tc<<<GT, 256, SMEM_TC, sA>>>(agg0, 0, agg2, 2, 3,
                                       bnet, bvec, Wl2, out, N_NODES);
    cudaEventRecord(eA3, sA);

    cudaStreamWaitEvent(sB, eAgg, 0);
    chain_tc<<<GT, 256, SMEM_TC, sB>>>(bcell, 1, agg1, 0, 2,
                                       bcell, bvec, Wl2, out + ND, N_NODES);
    cudaEventRecord(eB3, sB);

    // ---- join back to origin stream ----
    cudaStreamWaitEvent(0, eA3, 0);
    cudaStreamWaitEvent(0, eB3, 0);
}